// round 3
// baseline (speedup 1.0000x reference)
#include <cuda_runtime.h>

#define NNODES 20000
#define NEDGES 320000
#define EPRIME (NNODES + NEDGES)   // 340000 (edges + self loops)

// ---------------- scratch (static device globals; no allocation) ----------------
__device__ int   g_deg[NNODES];
__device__ int   g_rowptr[NNODES + 1];
__device__ int   g_cursor[NNODES];
__device__ int   g_eid[EPRIME];
__device__ float g_dis[NNODES];
__device__ float g_xw[NNODES * 256];
__device__ float g_h0[NNODES * 64];
__device__ float g_h1[NNODES * 256];
__device__ float g_h2[NNODES * 64];
__device__ float g_als[NNODES * 4];
__device__ float g_ald[NNODES * 4];

__device__ __forceinline__ float lrelu(float v) { return v > 0.f ? v : 0.2f * v; }
__device__ __forceinline__ int esrc(int e, const int* __restrict__ ei) {
    return (e < NEDGES) ? ei[e] : (e - NEDGES);
}
__device__ __forceinline__ int edst(int e, const int* __restrict__ ei) {
    return (e < NEDGES) ? ei[NEDGES + e] : (e - NEDGES);
}

// ---------------- CSR build ----------------
__global__ void k_zero_deg() {
    int i = blockIdx.x * blockDim.x + threadIdx.x;
    if (i < NNODES) g_deg[i] = 0;
}

__global__ void k_count(const int* __restrict__ ei) {
    int e = blockIdx.x * blockDim.x + threadIdx.x;
    if (e < EPRIME) atomicAdd(&g_deg[edst(e, ei)], 1);
}

// single block, 1024 threads: exclusive scan of deg -> rowptr, cursor
__global__ void k_scan() {
    const int CH = (NNODES + 1023) / 1024;  // 20
    __shared__ int sums[1024];
    int t = threadIdx.x;
    int base = t * CH;
    int local[CH];
    int s = 0;
#pragma unroll
    for (int i = 0; i < CH; i++) {
        int idx = base + i;
        int v = (idx < NNODES) ? g_deg[idx] : 0;
        local[i] = s;
        s += v;
    }
    sums[t] = s;
    __syncthreads();
    for (int off = 1; off < 1024; off <<= 1) {
        int v = (t >= off) ? sums[t - off] : 0;
        __syncthreads();
        sums[t] += v;
        __syncthreads();
    }
    int offset = (t > 0) ? sums[t - 1] : 0;
#pragma unroll
    for (int i = 0; i < CH; i++) {
        int idx = base + i;
        if (idx < NNODES) {
            int r = offset + local[i];
            g_rowptr[idx] = r;
            g_cursor[idx] = r;
        }
    }
    if (t == 1023) g_rowptr[NNODES] = sums[1023];
}

__global__ void k_scatter(const int* __restrict__ ei) {
    int e = blockIdx.x * blockDim.x + threadIdx.x;
    if (e < EPRIME) {
        int pos = atomicAdd(&g_cursor[edst(e, ei)], 1);
        g_eid[pos] = e;
    }
}

__global__ void k_dis() {
    int n = blockIdx.x * blockDim.x + threadIdx.x;
    if (n < NNODES) g_dis[n] = rsqrtf((float)g_deg[n]);  // deg >= 1 (self loops)
}

// ---------------- fp32 tiled SGEMM: C[M,N] = A[M,K] @ B[K,N] ----------------
// 64x64 tile, BK=16, 256 threads, 4x4 per thread. K % 16 == 0, N % 64 == 0.
__global__ void k_sgemm(const float* __restrict__ A, const float* __restrict__ B,
                        float* __restrict__ C, int M, int N, int K) {
    const int BM = 64, BN = 64, BK = 16;
    __shared__ float As[BK][BM + 1];
    __shared__ float Bs[BK][BN];
    int t = threadIdx.x;
    int bm = blockIdx.y * BM, bn = blockIdx.x * BN;
    int tx = t & 15, ty = t >> 4;
    float acc[4][4] = {};
    for (int k0 = 0; k0 < K; k0 += BK) {
#pragma unroll
        for (int i = 0; i < 4; i++) {
            int idx = i * 256 + t;
            int r = idx >> 4, k = idx & 15;
            int row = bm + r;
            As[k][r] = (row < M) ? A[row * K + k0 + k] : 0.f;
            int kk = idx >> 6, c = idx & 63;
            Bs[kk][c] = B[(k0 + kk) * N + bn + c];
        }
        __syncthreads();
#pragma unroll
        for (int k = 0; k < BK; k++) {
            float ra[4], rb[4];
#pragma unroll
            for (int i = 0; i < 4; i++) ra[i] = As[k][ty * 4 + i];
#pragma unroll
            for (int j = 0; j < 4; j++) rb[j] = Bs[k][tx * 4 + j];
#pragma unroll
            for (int i = 0; i < 4; i++)
#pragma unroll
                for (int j = 0; j < 4; j++) acc[i][j] += ra[i] * rb[j];
        }
        __syncthreads();
    }
#pragma unroll
    for (int i = 0; i < 4; i++) {
        int row = bm + ty * 4 + i;
        if (row < M) {
#pragma unroll
            for (int j = 0; j < 4; j++) C[row * N + bn + tx * 4 + j] = acc[i][j];
        }
    }
}

// ---------------- GCN aggregate: h0 = relu(dis[n]*sum(dis[s]*xw[s]) + b) ----------------
__global__ void k_gcn(const float* __restrict__ xw, const int* __restrict__ ei,
                      const float* __restrict__ b) {
    int warp = (blockIdx.x * blockDim.x + threadIdx.x) >> 5;
    int lane = threadIdx.x & 31;
    if (warp >= NNODES) return;
    int n = warp;
    int beg = g_rowptr[n], end = g_rowptr[n + 1];
    float a0 = 0.f, a1 = 0.f;
    for (int idx = beg; idx < end; idx++) {
        int e = g_eid[idx];
        int s = esrc(e, ei);
        float w = g_dis[s];
        float2 v = *(const float2*)&xw[s * 64 + lane * 2];
        a0 += w * v.x;
        a1 += w * v.y;
    }
    float dn = g_dis[n];
    float o0 = dn * a0 + b[lane * 2];
    float o1 = dn * a1 + b[lane * 2 + 1];
    g_h0[n * 64 + lane * 2]     = fmaxf(o0, 0.f);
    g_h0[n * 64 + lane * 2 + 1] = fmaxf(o1, 0.f);
}

// ---------------- attention pre: als/ald [N,4] from xw [N,256] ----------------
__global__ void k_attn(const float* __restrict__ xw, const float* __restrict__ asrc,
                       const float* __restrict__ adst) {
    int warp = (blockIdx.x * blockDim.x + threadIdx.x) >> 5;
    int lane = threadIdx.x & 31;
    if (warp >= NNODES) return;
    int n = warp;
    int c = lane * 8;
    const float4* xr = (const float4*)&xw[n * 256 + c];
    const float4* sr = (const float4*)&asrc[c];
    const float4* dr = (const float4*)&adst[c];
    float4 xa = xr[0], xb = xr[1];
    float4 sa = sr[0], sb = sr[1];
    float4 da = dr[0], db = dr[1];
    float ps = xa.x * sa.x + xa.y * sa.y + xa.z * sa.z + xa.w * sa.w +
               xb.x * sb.x + xb.y * sb.y + xb.z * sb.z + xb.w * sb.w;
    float pd = xa.x * da.x + xa.y * da.y + xa.z * da.z + xa.w * da.w +
               xb.x * db.x + xb.y * db.y + xb.z * db.z + xb.w * db.w;
#pragma unroll
    for (int off = 4; off; off >>= 1) {
        ps += __shfl_xor_sync(0xffffffffu, ps, off);
        pd += __shfl_xor_sync(0xffffffffu, pd, off);
    }
    if ((lane & 7) == 0) {
        int h = lane >> 3;
        g_als[n * 4 + h] = ps;
        g_ald[n * 4 + h] = pd;
    }
}

// ---------------- GAT aggregate (softmax + weighted sum), one warp per dst node ----
// mode 0: concat (out 256) + relu; mode 1: head-mean (out 64) + relu; mode 2: head-mean
__global__ void k_gat(const float* __restrict__ xw, const int* __restrict__ ei,
                      const float* __restrict__ bias, float* __restrict__ alpha_out,
                      float* __restrict__ hout, int mode) {
    int warp = (blockIdx.x * blockDim.x + threadIdx.x) >> 5;
    int lane = threadIdx.x & 31;
    if (warp >= NNODES) return;
    int n = warp;
    int beg = g_rowptr[n], end = g_rowptr[n + 1];
    float4 ad = *(const float4*)&g_ald[n * 4];

    // pass 1: per-head max of leaky logits
    float m0 = -1e30f, m1 = -1e30f, m2 = -1e30f, m3 = -1e30f;
    for (int idx = beg + lane; idx < end; idx += 32) {
        int e = g_eid[idx];
        int s = esrc(e, ei);
        float4 as4 = *(const float4*)&g_als[s * 4];
        m0 = fmaxf(m0, lrelu(as4.x + ad.x));
        m1 = fmaxf(m1, lrelu(as4.y + ad.y));
        m2 = fmaxf(m2, lrelu(as4.z + ad.z));
        m3 = fmaxf(m3, lrelu(as4.w + ad.w));
    }
#pragma unroll
    for (int off = 16; off; off >>= 1) {
        m0 = fmaxf(m0, __shfl_xor_sync(0xffffffffu, m0, off));
        m1 = fmaxf(m1, __shfl_xor_sync(0xffffffffu, m1, off));
        m2 = fmaxf(m2, __shfl_xor_sync(0xffffffffu, m2, off));
        m3 = fmaxf(m3, __shfl_xor_sync(0xffffffffu, m3, off));
    }

    // pass 2: per-head sum of exp
    float s0 = 0.f, s1 = 0.f, s2 = 0.f, s3 = 0.f;
    for (int idx = beg + lane; idx < end; idx += 32) {
        int e = g_eid[idx];
        int s = esrc(e, ei);
        float4 as4 = *(const float4*)&g_als[s * 4];
        s0 += expf(lrelu(as4.x + ad.x) - m0);
        s1 += expf(lrelu(as4.y + ad.y) - m1);
        s2 += expf(lrelu(as4.z + ad.z) - m2);
        s3 += expf(lrelu(as4.w + ad.w) - m3);
    }
#pragma unroll
    for (int off = 16; off; off >>= 1) {
        s0 += __shfl_xor_sync(0xffffffffu, s0, off);
        s1 += __shfl_xor_sync(0xffffffffu, s1, off);
        s2 += __shfl_xor_sync(0xffffffffu, s2, off);
        s3 += __shfl_xor_sync(0xffffffffu, s3, off);
    }
    float i0 = 1.f / (s0 + 1e-16f);
    float i1 = 1.f / (s1 + 1e-16f);
    float i2 = 1.f / (s2 + 1e-16f);
    float i3 = 1.f / (s3 + 1e-16f);

    // pass 3: aggregate. lane covers channels [lane*8, lane*8+8); head = lane>>3
    int head = lane >> 3;
    float4 accA = make_float4(0.f, 0.f, 0.f, 0.f);
    float4 accB = make_float4(0.f, 0.f, 0.f, 0.f);
    for (int idx = beg; idx < end; idx++) {
        int e = g_eid[idx];
        int s = esrc(e, ei);
        float4 as4 = *(const float4*)&g_als[s * 4];
        float a0 = expf(lrelu(as4.x + ad.x) - m0) * i0;
        float a1 = expf(lrelu(as4.y + ad.y) - m1) * i1;
        float a2 = expf(lrelu(as4.z + ad.z) - m2) * i2;
        float a3 = expf(lrelu(as4.w + ad.w) - m3) * i3;
        if (lane < 4) {
            float av = (lane == 0) ? a0 : (lane == 1) ? a1 : (lane == 2) ? a2 : a3;
            alpha_out[e * 4 + lane] = av;
        }
        float myA = (head == 0) ? a0 : (head == 1) ? a1 : (head == 2) ? a2 : a3;
        const float4* xr = (const float4*)&xw[s * 256 + lane * 8];
        float4 xa = xr[0], xb = xr[1];
        accA.x += myA * xa.x; accA.y += myA * xa.y; accA.z += myA * xa.z; accA.w += myA * xa.w;
        accB.x += myA * xb.x; accB.y += myA * xb.y; accB.z += myA * xb.z; accB.w += myA * xb.w;
    }

    if (mode == 0) {
        int c = lane * 8;
        float4 bA = *(const float4*)&bias[c];
        float4 bB = *(const float4*)&bias[c + 4];
        float4 oA = make_float4(fmaxf(accA.x + bA.x, 0.f), fmaxf(accA.y + bA.y, 0.f),
                                fmaxf(accA.z + bA.z, 0.f), fmaxf(accA.w + bA.w, 0.f));
        float4 oB = make_float4(fmaxf(accB.x + bB.x, 0.f), fmaxf(accB.y + bB.y, 0.f),
                                fmaxf(accB.z + bB.z, 0.f), fmaxf(accB.w + bB.w, 0.f));
        *(float4*)&hout[n * 256 + c] = oA;
        *(float4*)&hout[n * 256 + c + 4] = oB;
    } else {
        // sum across heads: lanes differing in bits 3,4 hold the other heads' copies
#pragma unroll
        for (int off = 8; off <= 16; off <<= 1) {
            accA.x += __shfl_xor_sync(0xffffffffu, accA.x, off);
            accA.y += __shfl_xor_sync(0xffffffffu, accA.y, off);
            accA.z += __shfl_xor_sync(0xffffffffu, accA.z, off);
            accA.w += __shfl_xor_sync(0xffffffffu, accA.w, off);
            accB.x += __shfl_xor_sync(0xffffffffu, accB.x, off);
            accB.y += __shfl_xor_sync(0xffffffffu, accB.y, off);
            accB.z += __shfl_xor_sync(0xffffffffu, accB.z, off);
            accB.w += __shfl_xor_sync(0xffffffffu, accB.w, off);
        }
        if (lane < 8) {
            int c = lane * 8;
            float4 bA = *(const float4*)&bias[c];
            float4 bB = *(const float4*)&bias[c + 4];
            float4 oA = make_float4(accA.x * 0.25f + bA.x, accA.y * 0.25f + bA.y,
                                    accA.z * 0.25f + bA.z, accA.w * 0.25f + bA.w);
            float4 oB = make_float4(accB.x * 0.25f + bB.x, accB.y * 0.25f + bB.y,
                                    accB.z * 0.25f + bB.z, accB.w * 0.25f + bB.w);
            if (mode == 1) {
                oA = make_float4(fmaxf(oA.x, 0.f), fmaxf(oA.y, 0.f), fmaxf(oA.z, 0.f), fmaxf(oA.w, 0.f));
                oB = make_float4(fmaxf(oB.x, 0.f), fmaxf(oB.y, 0.f), fmaxf(oB.z, 0.f), fmaxf(oB.w, 0.f));
            }
            *(float4*)&hout[n * 64 + c] = oA;
            *(float4*)&hout[n * 64 + c + 4] = oB;
        }
    }
}

// ---------------- host ----------------
extern "C" void kernel_launch(void* const* d_in, const int* in_sizes, int n_in,
                              void* d_out, int out_size) {
    const float* x      = (const float*)d_in[0];
    const int*   ei     = (const int*)d_in[1];
    const float* gcn_W  = (const float*)d_in[2];
    const float* gcn_b  = (const float*)d_in[3];
    const float* g1_W   = (const float*)d_in[4];
    const float* g1_as  = (const float*)d_in[5];
    const float* g1_ad  = (const float*)d_in[6];
    const float* g1_b   = (const float*)d_in[7];
    const float* g2_W   = (const float*)d_in[8];
    const float* g2_as  = (const float*)d_in[9];
    const float* g2_ad  = (const float*)d_in[10];
    const float* g2_b   = (const float*)d_in[11];
    const float* m_W    = (const float*)d_in[12];
    const float* m_as   = (const float*)d_in[13];
    const float* m_ad   = (const float*)d_in[14];
    const float* m_b    = (const float*)d_in[15];
    const float* s_W    = (const float*)d_in[16];
    const float* s_as   = (const float*)d_in[17];
    const float* s_ad   = (const float*)d_in[18];
    const float* s_b    = (const float*)d_in[19];

    float* out    = (float*)d_out;
    float* z_mean = out;
    float* z_std  = out + (size_t)NNODES * 64;
    float* a1     = out + (size_t)NNODES * 128;
    float* a2     = a1 + (size_t)EPRIME * 4;
    float* am     = a2 + (size_t)EPRIME * 4;
    float* as     = am + (size_t)EPRIME * 4;

    float *p_xw, *p_h0, *p_h1, *p_h2;
    cudaGetSymbolAddress((void**)&p_xw, g_xw);
    cudaGetSymbolAddress((void**)&p_h0, g_h0);
    cudaGetSymbolAddress((void**)&p_h1, g_h1);
    cudaGetSymbolAddress((void**)&p_h2, g_h2);

    const int TB = 256;
    int nodeBlocks = (NNODES + TB - 1) / TB;             // elementwise over nodes
    int edgeBlocks = (EPRIME + TB - 1) / TB;             // elementwise over edges
    int warpBlocks = (NNODES * 32 + TB - 1) / TB;        // one warp per node

    // CSR build
    k_zero_deg<<<nodeBlocks, TB>>>();
    k_count<<<edgeBlocks, TB>>>(ei);
    k_scan<<<1, 1024>>>();
    k_scatter<<<edgeBlocks, TB>>>(ei);
    k_dis<<<nodeBlocks, TB>>>();

    dim3 g64(1, (NNODES + 63) / 64), g256(4, (NNODES + 63) / 64);

    // GCN
    k_sgemm<<<g64, 256>>>(x, gcn_W, p_xw, NNODES, 64, 128);
    k_gcn<<<warpBlocks, TB>>>(p_xw, ei, gcn_b);

    // GAT1 (concat + relu)
    k_sgemm<<<g256, 256>>>(p_h0, g1_W, p_xw, NNODES, 256, 64);
    k_attn<<<warpBlocks, TB>>>(p_xw, g1_as, g1_ad);
    k_gat<<<warpBlocks, TB>>>(p_xw, ei, g1_b, a1, p_h1, 0);

    // GAT2 (mean + relu)
    k_sgemm<<<g256, 256>>>(p_h1, g2_W, p_xw, NNODES, 256, 256);
    k_attn<<<warpBlocks, TB>>>(p_xw, g2_as, g2_ad);
    k_gat<<<warpBlocks, TB>>>(p_xw, ei, g2_b, a2, p_h2, 1);

    // mean head (mean, no relu)
    k_sgemm<<<g256, 256>>>(p_h2, m_W, p_xw, NNODES, 256, 64);
    k_attn<<<warpBlocks, TB>>>(p_xw, m_as, m_ad);
    k_gat<<<warpBlocks, TB>>>(p_xw, ei, m_b, am, z_mean, 2);

    // std head (mean, no relu)
    k_sgemm<<<g256, 256>>>(p_h2, s_W, p_xw, NNODES, 256, 64);
    k_attn<<<warpBlocks, TB>>>(p_xw, s_as, s_ad);
    k_gat<<<warpBlocks, TB>>>(p_xw, ei, s_b, as, z_std, 2);
}

// round 4
// speedup vs baseline: 1.3533x; 1.3533x over previous
#include <cuda_runtime.h>

#define NNODES 20000
#define NEDGES 320000
#define EPRIME (NNODES + NEDGES)   // 340000 (edges + self loops)

// ---------------- scratch (static device globals; no allocation) ----------------
__device__ int   g_deg[NNODES];
__device__ int   g_rowptr[NNODES + 1];
__device__ int   g_cursor[NNODES];
__device__ int   g_eid[EPRIME];
__device__ float g_dis[NNODES];
__device__ float g_xw[NNODES * 256];
__device__ float g_h0[NNODES * 64];
__device__ float g_h1[NNODES * 256];
__device__ float g_h2[NNODES * 64];
__device__ float g_als[NNODES * 4];
__device__ float g_ald[NNODES * 4];

__device__ __forceinline__ float lrelu(float v) { return v > 0.f ? v : 0.2f * v; }
__device__ __forceinline__ int esrc(int e, const int* __restrict__ ei) {
    return (e < NEDGES) ? ei[e] : (e - NEDGES);
}
__device__ __forceinline__ int edst(int e, const int* __restrict__ ei) {
    return (e < NEDGES) ? ei[NEDGES + e] : (e - NEDGES);
}

// ---------------- CSR build ----------------
__global__ void k_count(const int* __restrict__ ei) {
    int e = blockIdx.x * blockDim.x + threadIdx.x;
    if (e < EPRIME) atomicAdd(&g_deg[edst(e, ei)], 1);
}

// single block, 1024 threads: exclusive scan of deg -> rowptr, cursor; also dis
__global__ void k_scan() {
    const int CH = (NNODES + 1023) / 1024;  // 20
    __shared__ int sums[1024];
    int t = threadIdx.x;
    int base = t * CH;
    int local[CH];
    int s = 0;
#pragma unroll
    for (int i = 0; i < CH; i++) {
        int idx = base + i;
        int v = (idx < NNODES) ? g_deg[idx] : 0;
        if (idx < NNODES) g_dis[idx] = rsqrtf((float)v);  // deg >= 1 (self loops)
        local[i] = s;
        s += v;
    }
    sums[t] = s;
    __syncthreads();
    for (int off = 1; off < 1024; off <<= 1) {
        int v = (t >= off) ? sums[t - off] : 0;
        __syncthreads();
        sums[t] += v;
        __syncthreads();
    }
    int offset = (t > 0) ? sums[t - 1] : 0;
#pragma unroll
    for (int i = 0; i < CH; i++) {
        int idx = base + i;
        if (idx < NNODES) {
            int r = offset + local[i];
            g_rowptr[idx] = r;
            g_cursor[idx] = r;
        }
    }
    if (t == 1023) g_rowptr[NNODES] = sums[1023];
}

__global__ void k_scatter(const int* __restrict__ ei) {
    int e = blockIdx.x * blockDim.x + threadIdx.x;
    if (e < EPRIME) {
        int pos = atomicAdd(&g_cursor[edst(e, ei)], 1);
        g_eid[pos] = e;
    }
}

// ---------------- fp32 tiled SGEMM: C[M,N] = A[M,K] @ B[K,N] ----------------
// 128x64 tile, BK=16, 256 threads, 8x4 per thread, double-buffered smem.
// K % 16 == 0, N % 64 == 0.
__global__ __launch_bounds__(256) void k_sgemm(const float* __restrict__ A,
                                               const float* __restrict__ B,
                                               float* __restrict__ C,
                                               int M, int N, int K) {
    __shared__ float As[2][16][132];
    __shared__ float Bs[2][16][64];
    int t = threadIdx.x;
    int bm = blockIdx.y * 128, bn = blockIdx.x * 64;
    int tx = t & 15, ty = t >> 4;
    int arow0 = t >> 2, akq = (t & 3) * 4;   // A: 2 float4 per thread
    int arow1 = arow0 + 64;
    int brow = t >> 4, bcol = (t & 15) * 4;  // B: 1 float4 per thread

    float4 rA0, rA1, rB;
    float acc[8][4] = {};

    // prologue fetch k0=0
    {
        int r0 = bm + arow0, r1 = bm + arow1;
        rA0 = (r0 < M) ? *(const float4*)&A[(size_t)r0 * K + akq] : make_float4(0.f, 0.f, 0.f, 0.f);
        rA1 = (r1 < M) ? *(const float4*)&A[(size_t)r1 * K + akq] : make_float4(0.f, 0.f, 0.f, 0.f);
        rB  = *(const float4*)&B[(size_t)brow * N + bn + bcol];
    }
    As[0][akq + 0][arow0] = rA0.x; As[0][akq + 1][arow0] = rA0.y;
    As[0][akq + 2][arow0] = rA0.z; As[0][akq + 3][arow0] = rA0.w;
    As[0][akq + 0][arow1] = rA1.x; As[0][akq + 1][arow1] = rA1.y;
    As[0][akq + 2][arow1] = rA1.z; As[0][akq + 3][arow1] = rA1.w;
    *(float4*)&Bs[0][brow][bcol] = rB;
    __syncthreads();

    int nk = K >> 4;
    for (int kt = 0; kt < nk; kt++) {
        int cur = kt & 1;
        if (kt + 1 < nk) {
            int k0 = (kt + 1) << 4;
            int r0 = bm + arow0, r1 = bm + arow1;
            rA0 = (r0 < M) ? *(const float4*)&A[(size_t)r0 * K + k0 + akq] : make_float4(0.f, 0.f, 0.f, 0.f);
            rA1 = (r1 < M) ? *(const float4*)&A[(size_t)r1 * K + k0 + akq] : make_float4(0.f, 0.f, 0.f, 0.f);
            rB  = *(const float4*)&B[(size_t)(k0 + brow) * N + bn + bcol];
        }
#pragma unroll
        for (int k = 0; k < 16; k++) {
            float4 a0 = *(const float4*)&As[cur][k][ty * 8];
            float4 a1 = *(const float4*)&As[cur][k][ty * 8 + 4];
            float4 b  = *(const float4*)&Bs[cur][k][tx * 4];
            float av[8] = {a0.x, a0.y, a0.z, a0.w, a1.x, a1.y, a1.z, a1.w};
            float bv[4] = {b.x, b.y, b.z, b.w};
#pragma unroll
            for (int i = 0; i < 8; i++)
#pragma unroll
                for (int j = 0; j < 4; j++) acc[i][j] += av[i] * bv[j];
        }
        if (kt + 1 < nk) {
            int nxt = cur ^ 1;
            As[nxt][akq + 0][arow0] = rA0.x; As[nxt][akq + 1][arow0] = rA0.y;
            As[nxt][akq + 2][arow0] = rA0.z; As[nxt][akq + 3][arow0] = rA0.w;
            As[nxt][akq + 0][arow1] = rA1.x; As[nxt][akq + 1][arow1] = rA1.y;
            As[nxt][akq + 2][arow1] = rA1.z; As[nxt][akq + 3][arow1] = rA1.w;
            *(float4*)&Bs[nxt][brow][bcol] = rB;
        }
        __syncthreads();
    }
#pragma unroll
    for (int i = 0; i < 8; i++) {
        int row = bm + ty * 8 + i;
        if (row < M)
            *(float4*)&C[(size_t)row * N + bn + tx * 4] =
                make_float4(acc[i][0], acc[i][1], acc[i][2], acc[i][3]);
    }
}

// ---------------- GCN aggregate: h0 = relu(dis[n]*sum(dis[s]*xw[s]) + b) ----------------
__global__ void k_gcn(const float* __restrict__ xw, const int* __restrict__ ei,
                      const float* __restrict__ b) {
    int warp = (blockIdx.x * blockDim.x + threadIdx.x) >> 5;
    int lane = threadIdx.x & 31;
    if (warp >= NNODES) return;
    int n = warp;
    int beg = g_rowptr[n], end = g_rowptr[n + 1];
    int cnt = end - beg;
    const unsigned FULL = 0xffffffffu;
    float a0 = 0.f, a1 = 0.f;

    if (cnt <= 128) {
        int   c_s[4];
        float c_w[4];
#pragma unroll
        for (int j = 0; j < 4; j++) {
            int idx = beg + j * 32 + lane;
            c_s[j] = 0; c_w[j] = 0.f;
            if (idx < end) {
                int e = g_eid[idx];
                int s = esrc(e, ei);
                c_s[j] = s;
                c_w[j] = g_dis[s];
            }
        }
#pragma unroll
        for (int j = 0; j < 4; j++) {
            int nj = cnt - j * 32;
            if (nj > 0) {
                if (nj > 32) nj = 32;
                int sj = c_s[j]; float wj = c_w[j];
                for (int tt = 0; tt < nj; tt++) {
                    int s   = __shfl_sync(FULL, sj, tt);
                    float w = __shfl_sync(FULL, wj, tt);
                    float2 v = *(const float2*)&xw[(size_t)s * 64 + lane * 2];
                    a0 += w * v.x;
                    a1 += w * v.y;
                }
            }
        }
    } else {
        for (int idx = beg; idx < end; idx++) {
            int e = g_eid[idx];
            int s = esrc(e, ei);
            float w = g_dis[s];
            float2 v = *(const float2*)&xw[(size_t)s * 64 + lane * 2];
            a0 += w * v.x;
            a1 += w * v.y;
        }
    }
    float dn = g_dis[n];
    float o0 = dn * a0 + b[lane * 2];
    float o1 = dn * a1 + b[lane * 2 + 1];
    g_h0[n * 64 + lane * 2]     = fmaxf(o0, 0.f);
    g_h0[n * 64 + lane * 2 + 1] = fmaxf(o1, 0.f);
}

// ---------------- attention pre: als/ald [N,4] from xw [N,256] ----------------
__global__ void k_attn(const float* __restrict__ xw, const float* __restrict__ asrc,
                       const float* __restrict__ adst) {
    int warp = (blockIdx.x * blockDim.x + threadIdx.x) >> 5;
    int lane = threadIdx.x & 31;
    if (warp >= NNODES) return;
    int n = warp;
    int c = lane * 8;
    const float4* xr = (const float4*)&xw[(size_t)n * 256 + c];
    const float4* sr = (const float4*)&asrc[c];
    const float4* dr = (const float4*)&adst[c];
    float4 xa = xr[0], xb = xr[1];
    float4 sa = sr[0], sb = sr[1];
    float4 da = dr[0], db = dr[1];
    float ps = xa.x * sa.x + xa.y * sa.y + xa.z * sa.z + xa.w * sa.w +
               xb.x * sb.x + xb.y * sb.y + xb.z * sb.z + xb.w * sb.w;
    float pd = xa.x * da.x + xa.y * da.y + xa.z * da.z + xa.w * da.w +
               xb.x * db.x + xb.y * db.y + xb.z * db.z + xb.w * db.w;
#pragma unroll
    for (int off = 4; off; off >>= 1) {
        ps += __shfl_xor_sync(0xffffffffu, ps, off);
        pd += __shfl_xor_sync(0xffffffffu, pd, off);
    }
    if ((lane & 7) == 0) {
        int h = lane >> 3;
        g_als[n * 4 + h] = ps;
        g_ald[n * 4 + h] = pd;
    }
}

// ---------------- GAT aggregate (softmax + weighted sum), one warp per dst node ----
// mode 0: concat (out 256) + relu; mode 1: head-mean (out 64) + relu; mode 2: head-mean
__global__ void k_gat(const float* __restrict__ xw, const int* __restrict__ ei,
                      const float* __restrict__ bias, float* __restrict__ alpha_out,
                      float* __restrict__ hout, int mode) {
    int warp = (blockIdx.x * blockDim.x + threadIdx.x) >> 5;
    int lane = threadIdx.x & 31;
    if (warp >= NNODES) return;
    int n = warp;
    int beg = g_rowptr[n], end = g_rowptr[n + 1];
    int cnt = end - beg;
    float4 ad = *(const float4*)&g_ald[n * 4];
    const unsigned FULL = 0xffffffffu;
    int head = lane >> 3;
    float4 accA = make_float4(0.f, 0.f, 0.f, 0.f);
    float4 accB = make_float4(0.f, 0.f, 0.f, 0.f);
    float i0, i1, i2, i3;

    if (cnt <= 128) {
        // ---- fast path: register-cached logits, exp computed once per edge ----
        int    c_src[4], c_e[4];
        float4 c_lg[4];
        float m0 = -1e30f, m1 = -1e30f, m2 = -1e30f, m3 = -1e30f;
#pragma unroll
        for (int j = 0; j < 4; j++) {
            int idx = beg + j * 32 + lane;
            c_src[j] = -1; c_e[j] = 0;
            c_lg[j] = make_float4(0.f, 0.f, 0.f, 0.f);
            if (idx < end) {
                int e = g_eid[idx];
                int s = esrc(e, ei);
                c_e[j] = e; c_src[j] = s;
                float4 as4 = *(const float4*)&g_als[s * 4];
                float4 lg = make_float4(lrelu(as4.x + ad.x), lrelu(as4.y + ad.y),
                                        lrelu(as4.z + ad.z), lrelu(as4.w + ad.w));
                c_lg[j] = lg;
                m0 = fmaxf(m0, lg.x); m1 = fmaxf(m1, lg.y);
                m2 = fmaxf(m2, lg.z); m3 = fmaxf(m3, lg.w);
            }
        }
#pragma unroll
        for (int off = 16; off; off >>= 1) {
            m0 = fmaxf(m0, __shfl_xor_sync(FULL, m0, off));
            m1 = fmaxf(m1, __shfl_xor_sync(FULL, m1, off));
            m2 = fmaxf(m2, __shfl_xor_sync(FULL, m2, off));
            m3 = fmaxf(m3, __shfl_xor_sync(FULL, m3, off));
        }
        float s0 = 0.f, s1 = 0.f, s2 = 0.f, s3 = 0.f;
#pragma unroll
        for (int j = 0; j < 4; j++) {
            if (c_src[j] >= 0) {
                float4 lg = c_lg[j];
                lg.x = expf(lg.x - m0); lg.y = expf(lg.y - m1);
                lg.z = expf(lg.z - m2); lg.w = expf(lg.w - m3);
                c_lg[j] = lg;
                s0 += lg.x; s1 += lg.y; s2 += lg.z; s3 += lg.w;
            }
        }
#pragma unroll
        for (int off = 16; off; off >>= 1) {
            s0 += __shfl_xor_sync(FULL, s0, off);
            s1 += __shfl_xor_sync(FULL, s1, off);
            s2 += __shfl_xor_sync(FULL, s2, off);
            s3 += __shfl_xor_sync(FULL, s3, off);
        }
        i0 = 1.f / (s0 + 1e-16f); i1 = 1.f / (s1 + 1e-16f);
        i2 = 1.f / (s2 + 1e-16f); i3 = 1.f / (s3 + 1e-16f);
        // write alphas (coalesced by owning lane)
#pragma unroll
        for (int j = 0; j < 4; j++) {
            if (c_src[j] >= 0) {
                float4 lg = c_lg[j];
                *(float4*)&alpha_out[(size_t)c_e[j] * 4] =
                    make_float4(lg.x * i0, lg.y * i1, lg.z * i2, lg.w * i3);
            }
        }
        // aggregate: broadcast alpha via shfl
#pragma unroll
        for (int j = 0; j < 4; j++) {
            int nj = cnt - j * 32;
            if (nj > 0) {
                if (nj > 32) nj = 32;
                int sj = c_src[j]; float4 lg = c_lg[j];
                for (int tt = 0; tt < nj; tt++) {
                    int s    = __shfl_sync(FULL, sj, tt);
                    float e0 = __shfl_sync(FULL, lg.x, tt);
                    float e1 = __shfl_sync(FULL, lg.y, tt);
                    float e2 = __shfl_sync(FULL, lg.z, tt);
                    float e3 = __shfl_sync(FULL, lg.w, tt);
                    float myA = (head == 0) ? e0 * i0 : (head == 1) ? e1 * i1
                              : (head == 2) ? e2 * i2 : e3 * i3;
                    const float4* xr = (const float4*)&xw[(size_t)s * 256 + lane * 8];
                    float4 xa = xr[0], xb = xr[1];
                    accA.x += myA * xa.x; accA.y += myA * xa.y;
                    accA.z += myA * xa.z; accA.w += myA * xa.w;
                    accB.x += myA * xb.x; accB.y += myA * xb.y;
                    accB.z += myA * xb.z; accB.w += myA * xb.w;
                }
            }
        }
    } else {
        // ---- fallback: 3-pass gather (deg > 128) ----
        float m0 = -1e30f, m1 = -1e30f, m2 = -1e30f, m3 = -1e30f;
        for (int idx = beg + lane; idx < end; idx += 32) {
            int e = g_eid[idx];
            int s = esrc(e, ei);
            float4 as4 = *(const float4*)&g_als[s * 4];
            m0 = fmaxf(m0, lrelu(as4.x + ad.x));
            m1 = fmaxf(m1, lrelu(as4.y + ad.y));
            m2 = fmaxf(m2, lrelu(as4.z + ad.z));
            m3 = fmaxf(m3, lrelu(as4.w + ad.w));
        }
#pragma unroll
        for (int off = 16; off; off >>= 1) {
            m0 = fmaxf(m0, __shfl_xor_sync(FULL, m0, off));
            m1 = fmaxf(m1, __shfl_xor_sync(FULL, m1, off));
            m2 = fmaxf(m2, __shfl_xor_sync(FULL, m2, off));
            m3 = fmaxf(m3, __shfl_xor_sync(FULL, m3, off));
        }
        float s0 = 0.f, s1 = 0.f, s2 = 0.f, s3 = 0.f;
        for (int idx = beg + lane; idx < end; idx += 32) {
            int e = g_eid[idx];
            int s = esrc(e, ei);
            float4 as4 = *(const float4*)&g_als[s * 4];
            s0 += expf(lrelu(as4.x + ad.x) - m0);
            s1 += expf(lrelu(as4.y + ad.y) - m1);
            s2 += expf(lrelu(as4.z + ad.z) - m2);
            s3 += expf(lrelu(as4.w + ad.w) - m3);
        }
#pragma unroll
        for (int off = 16; off; off >>= 1) {
            s0 += __shfl_xor_sync(FULL, s0, off);
            s1 += __shfl_xor_sync(FULL, s1, off);
            s2 += __shfl_xor_sync(FULL, s2, off);
            s3 += __shfl_xor_sync(FULL, s3, off);
        }
        i0 = 1.f / (s0 + 1e-16f); i1 = 1.f / (s1 + 1e-16f);
        i2 = 1.f / (s2 + 1e-16f); i3 = 1.f / (s3 + 1e-16f);
        for (int idx = beg; idx < end; idx++) {
            int e = g_eid[idx];
            int s = esrc(e, ei);
            float4 as4 = *(const float4*)&g_als[s * 4];
            float a0 = expf(lrelu(as4.x + ad.x) - m0) * i0;
            float a1 = expf(lrelu(as4.y + ad.y) - m1) * i1;
            float a2 = expf(lrelu(as4.z + ad.z) - m2) * i2;
            float a3 = expf(lrelu(as4.w + ad.w) - m3) * i3;
            if (lane < 4) {
                float av = (lane == 0) ? a0 : (lane == 1) ? a1 : (lane == 2) ? a2 : a3;
                alpha_out[(size_t)e * 4 + lane] = av;
            }
            float myA = (head == 0) ? a0 : (head == 1) ? a1 : (head == 2) ? a2 : a3;
            const float4* xr = (const float4*)&xw[(size_t)s * 256 + lane * 8];
            float4 xa = xr[0], xb = xr[1];
            accA.x += myA * xa.x; accA.y += myA * xa.y;
            accA.z += myA * xa.z; accA.w += myA * xa.w;
            accB.x += myA * xb.x; accB.y += myA * xb.y;
            accB.z += myA * xb.z; accB.w += myA * xb.w;
        }
    }

    // ---- epilogue ----
    if (mode == 0) {
        int c = lane * 8;
        float4 bA = *(const float4*)&bias[c];
        float4 bB = *(const float4*)&bias[c + 4];
        float4 oA = make_float4(fmaxf(accA.x + bA.x, 0.f), fmaxf(accA.y + bA.y, 0.f),
                                fmaxf(accA.z + bA.z, 0.f), fmaxf(accA.w + bA.w, 0.f));
        float4 oB = make_float4(fmaxf(accB.x + bB.x, 0.f), fmaxf(accB.y + bB.y, 0.f),
                                fmaxf(accB.z + bB.z, 0.f), fmaxf(accB.w + bB.w, 0.f));
        *(float4*)&hout[(size_t)n * 256 + c] = oA;
        *(float4*)&hout[(size_t)n * 256 + c + 4] = oB;
    } else {
        // sum across heads: lanes differing in bits 3,4 hold the other heads' copies
#pragma unroll
        for (int off = 8; off <= 16; off <<= 1) {
            accA.x += __shfl_xor_sync(FULL, accA.x, off);
            accA.y += __shfl_xor_sync(FULL, accA.y, off);
            accA.z += __shfl_xor_sync(FULL, accA.z, off);
            accA.w += __shfl_xor_sync(FULL, accA.w, off);
            accB.x += __shfl_xor_sync(FULL, accB.x, off);
            accB.y += __shfl_xor_sync(FULL, accB.y, off);
            accB.z += __shfl_xor_sync(FULL, accB.z, off);
            accB.w += __shfl_xor_sync(FULL, accB.w, off);
        }
        if (lane < 8) {
            int c = lane * 8;
            float4 bA = *(const float4*)&bias[c];
            float4 bB = *(const float4*)&bias[c + 4];
            float4 oA = make_float4(accA.x * 0.25f + bA.x, accA.y * 0.25f + bA.y,
                                    accA.z * 0.25f + bA.z, accA.w * 0.25f + bA.w);
            float4 oB = make_float4(accB.x * 0.25f + bB.x, accB.y * 0.25f + bB.y,
                                    accB.z * 0.25f + bB.z, accB.w * 0.25f + bB.w);
            if (mode == 1) {
                oA = make_float4(fmaxf(oA.x, 0.f), fmaxf(oA.y, 0.f), fmaxf(oA.z, 0.f), fmaxf(oA.w, 0.f));
                oB = make_float4(fmaxf(oB.x, 0.f), fmaxf(oB.y, 0.f), fmaxf(oB.z, 0.f), fmaxf(oB.w, 0.f));
            }
            *(float4*)&hout[(size_t)n * 64 + c] = oA;
            *(float4*)&hout[(size_t)n * 64 + c + 4] = oB;
        }
    }
}

// ---------------- host ----------------
extern "C" void kernel_launch(void* const* d_in, const int* in_sizes, int n_in,
                              void* d_out, int out_size) {
    const float* x      = (const float*)d_in[0];
    const int*   ei     = (const int*)d_in[1];
    const float* gcn_W  = (const float*)d_in[2];
    const float* gcn_b  = (const float*)d_in[3];
    const float* g1_W   = (const float*)d_in[4];
    const float* g1_as  = (const float*)d_in[5];
    const float* g1_ad  = (const float*)d_in[6];
    const float* g1_b   = (const float*)d_in[7];
    const float* g2_W   = (const float*)d_in[8];
    const float* g2_as  = (const float*)d_in[9];
    const float* g2_ad  = (const float*)d_in[10];
    const float* g2_b   = (const float*)d_in[11];
    const float* m_W    = (const float*)d_in[12];
    const float* m_as   = (const float*)d_in[13];
    const float* m_ad   = (const float*)d_in[14];
    const float* m_b    = (const float*)d_in[15];
    const float* s_W    = (const float*)d_in[16];
    const float* s_as   = (const float*)d_in[17];
    const float* s_ad   = (const float*)d_in[18];
    const float* s_b    = (const float*)d_in[19];

    float* out    = (float*)d_out;
    float* z_mean = out;
    float* z_std  = out + (size_t)NNODES * 64;
    float* a1     = out + (size_t)NNODES * 128;
    float* a2     = a1 + (size_t)EPRIME * 4;
    float* am     = a2 + (size_t)EPRIME * 4;
    float* as     = am + (size_t)EPRIME * 4;

    float *p_xw, *p_h0, *p_h1, *p_h2;
    int   *p_deg;
    cudaGetSymbolAddress((void**)&p_xw, g_xw);
    cudaGetSymbolAddress((void**)&p_h0, g_h0);
    cudaGetSymbolAddress((void**)&p_h1, g_h1);
    cudaGetSymbolAddress((void**)&p_h2, g_h2);
    cudaGetSymbolAddress((void**)&p_deg, g_deg);

    const int TB = 256;
    int edgeBlocks = (EPRIME + TB - 1) / TB;             // elementwise over edges
    int warpBlocks = (NNODES * 32 + TB - 1) / TB;        // one warp per node

    // CSR build
    cudaMemsetAsync(p_deg, 0, NNODES * sizeof(int));
    k_count<<<edgeBlocks, TB>>>(ei);
    k_scan<<<1, 1024>>>();
    k_scatter<<<edgeBlocks, TB>>>(ei);

    dim3 g64(1, (NNODES + 127) / 128), g256(4, (NNODES + 127) / 128);

    // GCN
    k_sgemm<<<g64, 256>>>(x, gcn_W, p_xw, NNODES, 64, 128);
    k_gcn<<<warpBlocks, TB>>>(p_xw, ei, gcn_b);

    // GAT1 (concat + relu)
    k_sgemm<<<g256, 256>>>(p_h0, g1_W, p_xw, NNODES, 256, 64);
    k_attn<<<warpBlocks, TB>>>(p_xw, g1_as, g1_ad);
    k_gat<<<warpBlocks, TB>>>(p_xw, ei, g1_b, a1, p_h1, 0);

    // GAT2 (mean + relu)
    k_sgemm<<<g256, 256>>>(p_h1, g2_W, p_xw, NNODES, 256, 256);
    k_attn<<<warpBlocks, TB>>>(p_xw, g2_as, g2_ad);
    k_gat<<<warpBlocks, TB>>>(p_xw, ei, g2_b, a2, p_h2, 1);

    // mean head (mean, no relu)
    k_sgemm<<<g256, 256>>>(p_h2, m_W, p_xw, NNODES, 256, 64);
    k_attn<<<warpBlocks, TB>>>(p_xw, m_as, m_ad);
    k_gat<<<warpBlocks, TB>>>(p_xw, ei, m_b, am, z_mean, 2);

    // std head (mean, no relu)
    k_sgemm<<<g256, 256>>>(p_h2, s_W, p_xw, NNODES, 256, 64);
    k_attn<<<warpBlocks, TB>>>(p_xw, s_as, s_ad);
    k_gat<<<warpBlocks, TB>>>(p_xw, ei, s_b, as, z_std, 2);
}

// round 9
// speedup vs baseline: 1.6616x; 1.2278x over previous
#include <cuda_runtime.h>

#define NNODES 20000
#define NEDGES 320000
#define EPRIME (NNODES + NEDGES)   // 340000 (edges + self loops)

// ---------------- scratch (static device globals; no allocation) ----------------
__device__ int   g_deg[NNODES];
__device__ int   g_rowptr[NNODES + 1];
__device__ int   g_cursor[NNODES];
__device__ int   g_eid[EPRIME];
__device__ float g_dis[NNODES];
__device__ float g_xw[NNODES * 256];
__device__ float g_h0[NNODES * 64];
__device__ float g_h1[NNODES * 256];
__device__ float g_h2[NNODES * 64];
__device__ float g_als[NNODES * 4];
__device__ float g_ald[NNODES * 4];

__device__ __forceinline__ float lrelu(float v) { return v > 0.f ? v : 0.2f * v; }
__device__ __forceinline__ int esrc(int e, const int* __restrict__ ei) {
    return (e < NEDGES) ? ei[e] : (e - NEDGES);
}
__device__ __forceinline__ int edst(int e, const int* __restrict__ ei) {
    return (e < NEDGES) ? ei[NEDGES + e] : (e - NEDGES);
}

// ---------------- CSR build ----------------
__global__ void k_count(const int* __restrict__ ei) {
    int e = blockIdx.x * blockDim.x + threadIdx.x;
    if (e < EPRIME) atomicAdd(&g_deg[edst(e, ei)], 1);
}

// single block, 1024 threads: exclusive scan of deg -> rowptr, cursor; also dis
__global__ void k_scan() {
    const int CH = (NNODES + 1023) / 1024;  // 20
    __shared__ int sums[1024];
    int t = threadIdx.x;
    int base = t * CH;
    int local[CH];
    int s = 0;
#pragma unroll
    for (int i = 0; i < CH; i++) {
        int idx = base + i;
        int v = (idx < NNODES) ? g_deg[idx] : 0;
        if (idx < NNODES) g_dis[idx] = rsqrtf((float)v);  // deg >= 1 (self loops)
        local[i] = s;
        s += v;
    }
    sums[t] = s;
    __syncthreads();
    for (int off = 1; off < 1024; off <<= 1) {
        int v = (t >= off) ? sums[t - off] : 0;
        __syncthreads();
        sums[t] += v;
        __syncthreads();
    }
    int offset = (t > 0) ? sums[t - 1] : 0;
#pragma unroll
    for (int i = 0; i < CH; i++) {
        int idx = base + i;
        if (idx < NNODES) {
            int r = offset + local[i];
            g_rowptr[idx] = r;
            g_cursor[idx] = r;
        }
    }
    if (t == 1023) g_rowptr[NNODES] = sums[1023];
}

__global__ void k_scatter(const int* __restrict__ ei) {
    int e = blockIdx.x * blockDim.x + threadIdx.x;
    if (e < EPRIME) {
        int pos = atomicAdd(&g_cursor[edst(e, ei)], 1);
        g_eid[pos] = e;
    }
}

// ---------------- tf32 tensor-core helpers ----------------
__device__ __forceinline__ float to_tf32(float x) {
    unsigned u;
    asm("cvt.rna.tf32.f32 %0, %1;" : "=r"(u) : "f"(x));
    return __uint_as_float(u);
}

__device__ __forceinline__ void mma8(float4& d, float a0, float a1, float a2, float a3,
                                     float b0, float b1) {
    asm volatile(
        "mma.sync.aligned.m16n8k8.row.col.f32.tf32.tf32.f32 "
        "{%0,%1,%2,%3}, {%4,%5,%6,%7}, {%8,%9}, {%0,%1,%2,%3};"
        : "+f"(d.x), "+f"(d.y), "+f"(d.z), "+f"(d.w)
        : "r"(__float_as_uint(a0)), "r"(__float_as_uint(a1)),
          "r"(__float_as_uint(a2)), "r"(__float_as_uint(a3)),
          "r"(__float_as_uint(b0)), "r"(__float_as_uint(b1)));
}

// ---------------- tf32 tiled GEMM: C[M,N] = A[M,K] @ B[K,N] ----------------
// 128x64 CTA tile, BK=16, 256 threads = 8 warps (4x2), warp tile 32x32.
// K % 16 == 0, N % 64 == 0. Inputs rounded to tf32 at smem fill; fp32 accum.
__global__ __launch_bounds__(256) void k_sgemm(const float* __restrict__ A,
                                               const float* __restrict__ B,
                                               float* __restrict__ C,
                                               int M, int N, int K) {
    __shared__ float As[2][128][20];  // [m][k], stride 20 (=4 mod 32): frag loads conflict-free
    __shared__ float Bs[2][16][72];   // [k][n], stride 72 (=8 mod 32): frag loads conflict-free
    int t = threadIdx.x;
    int bm = blockIdx.y * 128, bn = blockIdx.x * 64;
    int warp = t >> 5, lane = t & 31;
    int wm = warp & 3, wn = warp >> 2;      // 4 warps along M, 2 along N
    int g = lane >> 2, tg = lane & 3;

    int arow0 = t >> 2, arow1 = arow0 + 64, akq = (t & 3) * 4;  // A: 2 float4/thread
    int brow = t >> 4, bcol = (t & 15) * 4;                      // B: 1 float4/thread

    float4 rA0, rA1, rB;
    float4 acc[2][4];
#pragma unroll
    for (int i = 0; i < 2; i++)
#pragma unroll
        for (int j = 0; j < 4; j++) acc[i][j] = make_float4(0.f, 0.f, 0.f, 0.f);

    // prologue fetch k0=0
    {
        int r0 = bm + arow0, r1 = bm + arow1;
        rA0 = (r0 < M) ? *(const float4*)&A[(size_t)r0 * K + akq] : make_float4(0.f, 0.f, 0.f, 0.f);
        rA1 = (r1 < M) ? *(const float4*)&A[(size_t)r1 * K + akq] : make_float4(0.f, 0.f, 0.f, 0.f);
        rB  = *(const float4*)&B[(size_t)brow * N + bn + bcol];
    }
    As[0][arow0][akq + 0] = to_tf32(rA0.x); As[0][arow0][akq + 1] = to_tf32(rA0.y);
    As[0][arow0][akq + 2] = to_tf32(rA0.z); As[0][arow0][akq + 3] = to_tf32(rA0.w);
    As[0][arow1][akq + 0] = to_tf32(rA1.x); As[0][arow1][akq + 1] = to_tf32(rA1.y);
    As[0][arow1][akq + 2] = to_tf32(rA1.z); As[0][arow1][akq + 3] = to_tf32(rA1.w);
    Bs[0][brow][bcol + 0] = to_tf32(rB.x);  Bs[0][brow][bcol + 1] = to_tf32(rB.y);
    Bs[0][brow][bcol + 2] = to_tf32(rB.z);  Bs[0][brow][bcol + 3] = to_tf32(rB.w);
    __syncthreads();

    int nk = K >> 4;
    for (int kt = 0; kt < nk; kt++) {
        int cur = kt & 1;
        if (kt + 1 < nk) {
            int k0 = (kt + 1) << 4;
            int r0 = bm + arow0, r1 = bm + arow1;
            rA0 = (r0 < M) ? *(const float4*)&A[(size_t)r0 * K + k0 + akq] : make_float4(0.f, 0.f, 0.f, 0.f);
            rA1 = (r1 < M) ? *(const float4*)&A[(size_t)r1 * K + k0 + akq] : make_float4(0.f, 0.f, 0.f, 0.f);
            rB  = *(const float4*)&B[(size_t)(k0 + brow) * N + bn + bcol];
        }
#pragma unroll
        for (int kk = 0; kk < 16; kk += 8) {
            float a[2][4];
#pragma unroll
            for (int mi = 0; mi < 2; mi++) {
                int m0 = wm * 32 + mi * 16;
                a[mi][0] = As[cur][m0 + g][kk + tg];
                a[mi][1] = As[cur][m0 + g + 8][kk + tg];
                a[mi][2] = As[cur][m0 + g][kk + tg + 4];
                a[mi][3] = As[cur][m0 + g + 8][kk + tg + 4];
            }
            float b[4][2];
#pragma unroll
            for (int ni = 0; ni < 4; ni++) {
                int n0 = wn * 32 + ni * 8;
                b[ni][0] = Bs[cur][kk + tg][n0 + g];
                b[ni][1] = Bs[cur][kk + tg + 4][n0 + g];
            }
#pragma unroll
            for (int mi = 0; mi < 2; mi++)
#pragma unroll
                for (int ni = 0; ni < 4; ni++)
                    mma8(acc[mi][ni], a[mi][0], a[mi][1], a[mi][2], a[mi][3],
                         b[ni][0], b[ni][1]);
        }
        if (kt + 1 < nk) {
            int nxt = cur ^ 1;
            As[nxt][arow0][akq + 0] = to_tf32(rA0.x); As[nxt][arow0][akq + 1] = to_tf32(rA0.y);
            As[nxt][arow0][akq + 2] = to_tf32(rA0.z); As[nxt][arow0][akq + 3] = to_tf32(rA0.w);
            As[nxt][arow1][akq + 0] = to_tf32(rA1.x); As[nxt][arow1][akq + 1] = to_tf32(rA1.y);
            As[nxt][arow1][akq + 2] = to_tf32(rA1.z); As[nxt][arow1][akq + 3] = to_tf32(rA1.w);
            Bs[nxt][brow][bcol + 0] = to_tf32(rB.x);  Bs[nxt][brow][bcol + 1] = to_tf32(rB.y);
            Bs[nxt][brow][bcol + 2] = to_tf32(rB.z);  Bs[nxt][brow][bcol + 3] = to_tf32(rB.w);
        }
        __syncthreads();
    }

    // epilogue: c0=(g,2tg) c1=(g,2tg+1) c2=(g+8,2tg) c3=(g+8,2tg+1)
#pragma unroll
    for (int mi = 0; mi < 2; mi++) {
        int r0 = bm + wm * 32 + mi * 16 + g;
        int r1 = r0 + 8;
#pragma unroll
        for (int ni = 0; ni < 4; ni++) {
            int c = bn + wn * 32 + ni * 8 + 2 * tg;
            if (r0 < M) *(float2*)&C[(size_t)r0 * N + c] = make_float2(acc[mi][ni].x, acc[mi][ni].y);
            if (r1 < M) *(float2*)&C[(size_t)r1 * N + c] = make_float2(acc[mi][ni].z, acc[mi][ni].w);
        }
    }
}

// ---------------- GCN aggregate: h0 = relu(dis[n]*sum(dis[s]*xw[s]) + b) ----------------
__global__ void k_gcn(const float* __restrict__ xw, const int* __restrict__ ei,
                      const float* __restrict__ b) {
    int warp = (blockIdx.x * blockDim.x + threadIdx.x) >> 5;
    int lane = threadIdx.x & 31;
    if (warp >= NNODES) return;
    int n = warp;
    int beg = g_rowptr[n], end = g_rowptr[n + 1];
    int cnt = end - beg;
    const unsigned FULL = 0xffffffffu;
    float a0 = 0.f, a1 = 0.f;

    if (cnt <= 128) {
        int   c_s[4];
        float c_w[4];
#pragma unroll
        for (int j = 0; j < 4; j++) {
            int idx = beg + j * 32 + lane;
            c_s[j] = 0; c_w[j] = 0.f;
            if (idx < end) {
                int e = g_eid[idx];
                int s = esrc(e, ei);
                c_s[j] = s;
                c_w[j] = g_dis[s];
            }
        }
#pragma unroll
        for (int j = 0; j < 4; j++) {
            int nj = cnt - j * 32;
            if (nj > 0) {
                if (nj > 32) nj = 32;
                int sj = c_s[j]; float wj = c_w[j];
                for (int tt = 0; tt < nj; tt++) {
                    int s   = __shfl_sync(FULL, sj, tt);
                    float w = __shfl_sync(FULL, wj, tt);
                    float2 v = *(const float2*)&xw[(size_t)s * 64 + lane * 2];
                    a0 += w * v.x;
                    a1 += w * v.y;
                }
            }
        }
    } else {
        for (int idx = beg; idx < end; idx++) {
            int e = g_eid[idx];
            int s = esrc(e, ei);
            float w = g_dis[s];
            float2 v = *(const float2*)&xw[(size_t)s * 64 + lane * 2];
            a0 += w * v.x;
            a1 += w * v.y;
        }
    }
    float dn = g_dis[n];
    float o0 = dn * a0 + b[lane * 2];
    float o1 = dn * a1 + b[lane * 2 + 1];
    g_h0[n * 64 + lane * 2]     = fmaxf(o0, 0.f);
    g_h0[n * 64 + lane * 2 + 1] = fmaxf(o1, 0.f);
}

// ---------------- attention pre: als/ald [N,4] from xw [N,256] ----------------
__global__ void k_attn(const float* __restrict__ xw, const float* __restrict__ asrc,
                       const float* __restrict__ adst) {
    int warp = (blockIdx.x * blockDim.x + threadIdx.x) >> 5;
    int lane = threadIdx.x & 31;
    if (warp >= NNODES) return;
    int n = warp;
    int c = lane * 8;
    const float4* xr = (const float4*)&xw[(size_t)n * 256 + c];
    const float4* sr = (const float4*)&asrc[c];
    const float4* dr = (const float4*)&adst[c];
    float4 xa = xr[0], xb = xr[1];
    float4 sa = sr[0], sb = sr[1];
    float4 da = dr[0], db = dr[1];
    float ps = xa.x * sa.x + xa.y * sa.y + xa.z * sa.z + xa.w * sa.w +
               xb.x * sb.x + xb.y * sb.y + xb.z * sb.z + xb.w * sb.w;
    float pd = xa.x * da.x + xa.y * da.y + xa.z * da.z + xa.w * da.w +
               xb.x * db.x + xb.y * db.y + xb.z * db.z + xb.w * db.w;
#pragma unroll
    for (int off = 4; off; off >>= 1) {
        ps += __shfl_xor_sync(0xffffffffu, ps, off);
        pd += __shfl_xor_sync(0xffffffffu, pd, off);
    }
    if ((lane & 7) == 0) {
        int h = lane >> 3;
        g_als[n * 4 + h] = ps;
        g_ald[n * 4 + h] = pd;
    }
}

// ---------------- GAT aggregate (softmax + weighted sum), one warp per dst node ----
// mode 0: concat (out 256) + relu; mode 1: head-mean (out 64) + relu; mode 2: head-mean
__global__ void k_gat(const float* __restrict__ xw, const int* __restrict__ ei,
                      const float* __restrict__ bias, float* __restrict__ alpha_out,
                      float* __restrict__ hout, int mode) {
    int warp = (blockIdx.x * blockDim.x + threadIdx.x) >> 5;
    int lane = threadIdx.x & 31;
    if (warp >= NNODES) return;
    int n = warp;
    int beg = g_rowptr[n], end = g_rowptr[n + 1];
    int cnt = end - beg;
    float4 ad = *(const float4*)&g_ald[n * 4];
    const unsigned FULL = 0xffffffffu;
    int head = lane >> 3;
    float4 accA = make_float4(0.f, 0.f, 0.f, 0.f);
    float4 accB = make_float4(0.f, 0.f, 0.f, 0.f);
    float i0, i1, i2, i3;

    if (cnt <= 128) {
        // ---- fast path: register-cached logits, exp computed once per edge ----
        int    c_src[4], c_e[4];
        float4 c_lg[4];
        float m0 = -1e30f, m1 = -1e30f, m2 = -1e30f, m3 = -1e30f;
#pragma unroll
        for (int j = 0; j < 4; j++) {
            int idx = beg + j * 32 + lane;
            c_src[j] = -1; c_e[j] = 0;
            c_lg[j] = make_float4(0.f, 0.f, 0.f, 0.f);
            if (idx < end) {
                int e = g_eid[idx];
                int s = esrc(e, ei);
                c_e[j] = e; c_src[j] = s;
                float4 as4 = *(const float4*)&g_als[s * 4];
                float4 lg = make_float4(lrelu(as4.x + ad.x), lrelu(as4.y + ad.y),
                                        lrelu(as4.z + ad.z), lrelu(as4.w + ad.w));
                c_lg[j] = lg;
                m0 = fmaxf(m0, lg.x); m1 = fmaxf(m1, lg.y);
                m2 = fmaxf(m2, lg.z); m3 = fmaxf(m3, lg.w);
            }
        }
#pragma unroll
        for (int off = 16; off; off >>= 1) {
            m0 = fmaxf(m0, __shfl_xor_sync(FULL, m0, off));
            m1 = fmaxf(m1, __shfl_xor_sync(FULL, m1, off));
            m2 = fmaxf(m2, __shfl_xor_sync(FULL, m2, off));
            m3 = fmaxf(m3, __shfl_xor_sync(FULL, m3, off));
        }
        float s0 = 0.f, s1 = 0.f, s2 = 0.f, s3 = 0.f;
#pragma unroll
        for (int j = 0; j < 4; j++) {
            if (c_src[j] >= 0) {
                float4 lg = c_lg[j];
                lg.x = expf(lg.x - m0); lg.y = expf(lg.y - m1);
                lg.z = expf(lg.z - m2); lg.w = expf(lg.w - m3);
                c_lg[j] = lg;
                s0 += lg.x; s1 += lg.y; s2 += lg.z; s3 += lg.w;
            }
        }
#pragma unroll
        for (int off = 16; off; off >>= 1) {
            s0 += __shfl_xor_sync(FULL, s0, off);
            s1 += __shfl_xor_sync(FULL, s1, off);
            s2 += __shfl_xor_sync(FULL, s2, off);
            s3 += __shfl_xor_sync(FULL, s3, off);
        }
        i0 = 1.f / (s0 + 1e-16f); i1 = 1.f / (s1 + 1e-16f);
        i2 = 1.f / (s2 + 1e-16f); i3 = 1.f / (s3 + 1e-16f);
        // write alphas (coalesced by owning lane)
#pragma unroll
        for (int j = 0; j < 4; j++) {
            if (c_src[j] >= 0) {
                float4 lg = c_lg[j];
                *(float4*)&alpha_out[(size_t)c_e[j] * 4] =
                    make_float4(lg.x * i0, lg.y * i1, lg.z * i2, lg.w * i3);
            }
        }
        // aggregate: broadcast alpha via shfl
#pragma unroll
        for (int j = 0; j < 4; j++) {
            int nj = cnt - j * 32;
            if (nj > 0) {
                if (nj > 32) nj = 32;
                int sj = c_src[j]; float4 lg = c_lg[j];
                for (int tt = 0; tt < nj; tt++) {
                    int s    = __shfl_sync(FULL, sj, tt);
                    float e0 = __shfl_sync(FULL, lg.x, tt);
                    float e1 = __shfl_sync(FULL, lg.y, tt);
                    float e2 = __shfl_sync(FULL, lg.z, tt);
                    float e3 = __shfl_sync(FULL, lg.w, tt);
                    float myA = (head == 0) ? e0 * i0 : (head == 1) ? e1 * i1
                              : (head == 2) ? e2 * i2 : e3 * i3;
                    const float4* xr = (const float4*)&xw[(size_t)s * 256 + lane * 8];
                    float4 xa = xr[0], xb = xr[1];
                    accA.x += myA * xa.x; accA.y += myA * xa.y;
                    accA.z += myA * xa.z; accA.w += myA * xa.w;
                    accB.x += myA * xb.x; accB.y += myA * xb.y;
                    accB.z += myA * xb.z; accB.w += myA * xb.w;
                }
            }
        }
    } else {
        // ---- fallback: 3-pass gather (deg > 128) ----
        float m0 = -1e30f, m1 = -1e30f, m2 = -1e30f, m3 = -1e30f;
        for (int idx = beg + lane; idx < end; idx += 32) {
            int e = g_eid[idx];
            int s = esrc(e, ei);
            float4 as4 = *(const float4*)&g_als[s * 4];
            m0 = fmaxf(m0, lrelu(as4.x + ad.x));
            m1 = fmaxf(m1, lrelu(as4.y + ad.y));
            m2 = fmaxf(m2, lrelu(as4.z + ad.z));
            m3 = fmaxf(m3, lrelu(as4.w + ad.w));
        }
#pragma unroll
        for (int off = 16; off; off >>= 1) {
            m0 = fmaxf(m0, __shfl_xor_sync(FULL, m0, off));
            m1 = fmaxf(m1, __shfl_xor_sync(FULL, m1, off));
            m2 = fmaxf(m2, __shfl_xor_sync(FULL, m2, off));
            m3 = fmaxf(m3, __shfl_xor_sync(FULL, m3, off));
        }
        float s0 = 0.f, s1 = 0.f, s2 = 0.f, s3 = 0.f;
        for (int idx = beg + lane; idx < end; idx += 32) {
            int e = g_eid[idx];
            int s = esrc(e, ei);
            float4 as4 = *(const float4*)&g_als[s * 4];
            s0 += expf(lrelu(as4.x + ad.x) - m0);
            s1 += expf(lrelu(as4.y + ad.y) - m1);
            s2 += expf(lrelu(as4.z + ad.z) - m2);
            s3 += expf(lrelu(as4.w + ad.w) - m3);
        }
#pragma unroll
        for (int off = 16; off; off >>= 1) {
            s0 += __shfl_xor_sync(FULL, s0, off);
            s1 += __shfl_xor_sync(FULL, s1, off);
            s2 += __shfl_xor_sync(FULL, s2, off);
            s3 += __shfl_xor_sync(FULL, s3, off);
        }
        i0 = 1.f / (s0 + 1e-16f); i1 = 1.f / (s1 + 1e-16f);
        i2 = 1.f / (s2 + 1e-16f); i3 = 1.f / (s3 + 1e-16f);
        for (int idx = beg; idx < end; idx++) {
            int e = g_eid[idx];
            int s = esrc(e, ei);
            float4 as4 = *(const float4*)&g_als[s * 4];
            float a0 = expf(lrelu(as4.x + ad.x) - m0) * i0;
            float a1 = expf(lrelu(as4.y + ad.y) - m1) * i1;
            float a2 = expf(lrelu(as4.z + ad.z) - m2) * i2;
            float a3 = expf(lrelu(as4.w + ad.w) - m3) * i3;
            if (lane < 4) {
                float av = (lane == 0) ? a0 : (lane == 1) ? a1 : (lane == 2) ? a2 : a3;
                alpha_out[(size_t)e * 4 + lane] = av;
            }
            float myA = (head == 0) ? a0 : (head == 1) ? a1 : (head == 2) ? a2 : a3;
            const float4* xr = (const float4*)&xw[(size_t)s * 256 + lane * 8];
            float4 xa = xr[0], xb = xr[1];
            accA.x += myA * xa.x; accA.y += myA * xa.y;
            accA.z += myA * xa.z; accA.w += myA * xa.w;
            accB.x += myA * xb.x; accB.y += myA * xb.y;
            accB.z += myA * xb.z; accB.w += myA * xb.w;
        }
    }

    // ---- epilogue ----
    if (mode == 0) {
        int c = lane * 8;
        float4 bA = *(const float4*)&bias[c];
        float4 bB = *(const float4*)&bias[c + 4];
        float4 oA = make_float4(fmaxf(accA.x + bA.x, 0.f), fmaxf(accA.y + bA.y, 0.f),
                                fmaxf(accA.z + bA.z, 0.f), fmaxf(accA.w + bA.w, 0.f));
        float4 oB = make_float4(fmaxf(accB.x + bB.x, 0.f), fmaxf(accB.y + bB.y, 0.f),
                                fmaxf(accB.z + bB.z, 0.f), fmaxf(accB.w + bB.w, 0.f));
        *(float4*)&hout[(size_t)n * 256 + c] = oA;
        *(float4*)&hout[(size_t)n * 256 + c + 4] = oB;
    } else {
        // sum across heads: lanes differing in bits 3,4 hold the other heads' copies
#pragma unroll
        for (int off = 8; off <= 16; off <<= 1) {
            accA.x += __shfl_xor_sync(FULL, accA.x, off);
            accA.y += __shfl_xor_sync(FULL, accA.y, off);
            accA.z += __shfl_xor_sync(FULL, accA.z, off);
            accA.w += __shfl_xor_sync(FULL, accA.w, off);
            accB.x += __shfl_xor_sync(FULL, accB.x, off);
            accB.y += __shfl_xor_sync(FULL, accB.y, off);
            accB.z += __shfl_xor_sync(FULL, accB.z, off);
            accB.w += __shfl_xor_sync(FULL, accB.w, off);
        }
        if (lane < 8) {
            int c = lane * 8;
            float4 bA = *(const float4*)&bias[c];
            float4 bB = *(const float4*)&bias[c + 4];
            float4 oA = make_float4(accA.x * 0.25f + bA.x, accA.y * 0.25f + bA.y,
                                    accA.z * 0.25f + bA.z, accA.w * 0.25f + bA.w);
            float4 oB = make_float4(accB.x * 0.25f + bB.x, accB.y * 0.25f + bB.y,
                                    accB.z * 0.25f + bB.z, accB.w * 0.25f + bB.w);
            if (mode == 1) {
                oA = make_float4(fmaxf(oA.x, 0.f), fmaxf(oA.y, 0.f), fmaxf(oA.z, 0.f), fmaxf(oA.w, 0.f));
                oB = make_float4(fmaxf(oB.x, 0.f), fmaxf(oB.y, 0.f), fmaxf(oB.z, 0.f), fmaxf(oB.w, 0.f));
            }
            *(float4*)&hout[(size_t)n * 64 + c] = oA;
            *(float4*)&hout[(size_t)n * 64 + c + 4] = oB;
        }
    }
}

// ---------------- host ----------------
extern "C" void kernel_launch(void* const* d_in, const int* in_sizes, int n_in,
                              void* d_out, int out_size) {
    const float* x      = (const float*)d_in[0];
    const int*   ei     = (const int*)d_in[1];
    const float* gcn_W  = (const float*)d_in[2];
    const float* gcn_b  = (const float*)d_in[3];
    const float* g1_W   = (const float*)d_in[4];
    const float* g1_as  = (const float*)d_in[5];
    const float* g1_ad  = (const float*)d_in[6];
    const float* g1_b   = (const float*)d_in[7];
    const float* g2_W   = (const float*)d_in[8];
    const float* g2_as  = (const float*)d_in[9];
    const float* g2_ad  = (const float*)d_in[10];
    const float* g2_b   = (const float*)d_in[11];
    const float* m_W    = (const float*)d_in[12];
    const float* m_as   = (const float*)d_in[13];
    const float* m_ad   = (const float*)d_in[14];
    const float* m_b    = (const float*)d_in[15];
    const float* s_W    = (const float*)d_in[16];
    const float* s_as   = (const float*)d_in[17];
    const float* s_ad   = (const float*)d_in[18];
    const float* s_b    = (const float*)d_in[19];

    float* out    = (float*)d_out;
    float* z_mean = out;
    float* z_std  = out + (size_t)NNODES * 64;
    float* a1     = out + (size_t)NNODES * 128;
    float* a2     = a1 + (size_t)EPRIME * 4;
    float* am     = a2 + (size_t)EPRIME * 4;
    float* as     = am + (size_t)EPRIME * 4;

    float *p_xw, *p_h0, *p_h1, *p_h2;
    int   *p_deg;
    cudaGetSymbolAddress((void**)&p_xw, g_xw);
    cudaGetSymbolAddress((void**)&p_h0, g_h0);
    cudaGetSymbolAddress((void**)&p_h1, g_h1);
    cudaGetSymbolAddress((void**)&p_h2, g_h2);
    cudaGetSymbolAddress((void**)&p_deg, g_deg);

    const int TB = 256;
    int edgeBlocks = (EPRIME + TB - 1) / TB;             // elementwise over edges
    int warpBlocks = (NNODES * 32 + TB - 1) / TB;        // one warp per node

    // CSR build
    cudaMemsetAsync(p_deg, 0, NNODES * sizeof(int));
    k_count<<<edgeBlocks, TB>>>(ei);
    k_scan<<<1, 1024>>>();
    k_scatter<<<edgeBlocks, TB>>>(ei);

    dim3 g64(1, (NNODES + 127) / 128), g256(4, (NNODES + 127) / 128);

    // GCN
    k_sgemm<<<g64, 256>>>(x, gcn_W, p_xw, NNODES, 64, 128);
    k_gcn<<<warpBlocks, TB>>>(p_xw, ei, gcn_b);

    // GAT1 (concat + relu)
    k_sgemm<<<g256, 256>>>(p_h0, g1_W, p_xw, NNODES, 256, 64);
    k_attn<<<warpBlocks, TB>>>(p_xw, g1_as, g1_ad);
    k_gat<<<warpBlocks, TB>>>(p_xw, ei, g1_b, a1, p_h1, 0);

    // GAT2 (mean + relu)
    k_sgemm<<<g256, 256>>>(p_h1, g2_W, p_xw, NNODES, 256, 256);
    k_attn<<<warpBlocks, TB>>>(p_xw, g2_as, g2_ad);
    k_gat<<<warpBlocks, TB>>>(p_xw, ei, g2_b, a2, p_h2, 1);

    // mean head (mean, no relu)
    k_sgemm<<<g256, 256>>>(p_h2, m_W, p_xw, NNODES, 256, 64);
    k_attn<<<warpBlocks, TB>>>(p_xw, m_as, m_ad);
    k_gat<<<warpBlocks, TB>>>(p_xw, ei, m_b, am, z_mean, 2);

    // std head (mean, no relu)
    k_sgemm<<<g256, 256>>>(p_h2, s_W, p_xw, NNODES, 256, 64);
    k_attn<<<warpBlocks, TB>>>(p_xw, s_as, s_ad);
    k_gat<<<warpBlocks, TB>>>(p_xw, ei, s_b, as, z_std, 2);
}

// round 10
// speedup vs baseline: 1.7540x; 1.0557x over previous
#include <cuda_runtime.h>

#define NNODES 20000
#define NEDGES 320000
#define EPRIME (NNODES + NEDGES)   // 340000 (edges + self loops)

// ---------------- scratch (static device globals; no allocation) ----------------
__device__ int   g_deg[NNODES];
__device__ int   g_rowptr[NNODES + 1];
__device__ int   g_cursor[NNODES];
__device__ int   g_eid[EPRIME];
__device__ float g_dis[NNODES];
__device__ float g_xw[NNODES * 256];
__device__ float g_xw2[NNODES * 256];   // second scratch for parallel std chain
__device__ float g_h0[NNODES * 64];
__device__ float g_h1[NNODES * 256];
__device__ float g_h2[NNODES * 64];
__device__ float g_als[NNODES * 4];
__device__ float g_ald[NNODES * 4];
__device__ float g_als2[NNODES * 4];
__device__ float g_ald2[NNODES * 4];

// ---------------- streams/events for graph-capture fork/join ----------------
static cudaStream_t g_s2;
static cudaEvent_t g_ev0, g_ev1, g_ev2, g_ev3;
namespace {
struct StreamInit {
    StreamInit() {
        cudaStreamCreateWithFlags(&g_s2, cudaStreamNonBlocking);
        cudaEventCreateWithFlags(&g_ev0, cudaEventDisableTiming);
        cudaEventCreateWithFlags(&g_ev1, cudaEventDisableTiming);
        cudaEventCreateWithFlags(&g_ev2, cudaEventDisableTiming);
        cudaEventCreateWithFlags(&g_ev3, cudaEventDisableTiming);
    }
};
StreamInit s_streamInit;
}

__device__ __forceinline__ float lrelu(float v) { return v > 0.f ? v : 0.2f * v; }
__device__ __forceinline__ int esrc(int e, const int* __restrict__ ei) {
    return (e < NEDGES) ? ei[e] : (e - NEDGES);
}
__device__ __forceinline__ int edst(int e, const int* __restrict__ ei) {
    return (e < NEDGES) ? ei[NEDGES + e] : (e - NEDGES);
}

// ---------------- CSR build ----------------
__global__ void k_count(const int* __restrict__ ei) {
    int e = blockIdx.x * blockDim.x + threadIdx.x;
    if (e < EPRIME) atomicAdd(&g_deg[edst(e, ei)], 1);
}

// single block, 1024 threads: exclusive scan of deg -> rowptr, cursor; also dis
__global__ void k_scan() {
    const int CH = (NNODES + 1023) / 1024;  // 20
    __shared__ int sums[1024];
    int t = threadIdx.x;
    int base = t * CH;
    int local[CH];
    int s = 0;
#pragma unroll
    for (int i = 0; i < CH; i++) {
        int idx = base + i;
        int v = (idx < NNODES) ? g_deg[idx] : 0;
        if (idx < NNODES) g_dis[idx] = rsqrtf((float)v);  // deg >= 1 (self loops)
        local[i] = s;
        s += v;
    }
    sums[t] = s;
    __syncthreads();
    for (int off = 1; off < 1024; off <<= 1) {
        int v = (t >= off) ? sums[t - off] : 0;
        __syncthreads();
        sums[t] += v;
        __syncthreads();
    }
    int offset = (t > 0) ? sums[t - 1] : 0;
#pragma unroll
    for (int i = 0; i < CH; i++) {
        int idx = base + i;
        if (idx < NNODES) {
            int r = offset + local[i];
            g_rowptr[idx] = r;
            g_cursor[idx] = r;
        }
    }
    if (t == 1023) g_rowptr[NNODES] = sums[1023];
}

__global__ void k_scatter(const int* __restrict__ ei) {
    int e = blockIdx.x * blockDim.x + threadIdx.x;
    if (e < EPRIME) {
        int pos = atomicAdd(&g_cursor[edst(e, ei)], 1);
        g_eid[pos] = e;
    }
}

// ---------------- tf32 tensor-core helpers ----------------
__device__ __forceinline__ float to_tf32(float x) {
    unsigned u;
    asm("cvt.rna.tf32.f32 %0, %1;" : "=r"(u) : "f"(x));
    return __uint_as_float(u);
}

__device__ __forceinline__ void mma8(float4& d, float a0, float a1, float a2, float a3,
                                     float b0, float b1) {
    asm volatile(
        "mma.sync.aligned.m16n8k8.row.col.f32.tf32.tf32.f32 "
        "{%0,%1,%2,%3}, {%4,%5,%6,%7}, {%8,%9}, {%0,%1,%2,%3};"
        : "+f"(d.x), "+f"(d.y), "+f"(d.z), "+f"(d.w)
        : "r"(__float_as_uint(a0)), "r"(__float_as_uint(a1)),
          "r"(__float_as_uint(a2)), "r"(__float_as_uint(a3)),
          "r"(__float_as_uint(b0)), "r"(__float_as_uint(b1)));
}

// ---------------- tf32 tiled GEMM: C[M,N] = A[M,K] @ B[K,N] ----------------
// 128x64 CTA tile, BK=16, 256 threads = 8 warps (4x2), warp tile 32x32.
// K % 16 == 0, N % 64 == 0. Inputs rounded to tf32 at smem fill; fp32 accum.
__global__ __launch_bounds__(256) void k_sgemm(const float* __restrict__ A,
                                               const float* __restrict__ B,
                                               float* __restrict__ C,
                                               int M, int N, int K) {
    __shared__ float As[2][128][20];  // [m][k], stride 20 (=4 mod 32): frag loads conflict-free
    __shared__ float Bs[2][16][72];   // [k][n], stride 72 (=8 mod 32): frag loads conflict-free
    int t = threadIdx.x;
    int bm = blockIdx.y * 128, bn = blockIdx.x * 64;
    int warp = t >> 5, lane = t & 31;
    int wm = warp & 3, wn = warp >> 2;      // 4 warps along M, 2 along N
    int g = lane >> 2, tg = lane & 3;

    int arow0 = t >> 2, arow1 = arow0 + 64, akq = (t & 3) * 4;  // A: 2 float4/thread
    int brow = t >> 4, bcol = (t & 15) * 4;                      // B: 1 float4/thread

    float4 rA0, rA1, rB;
    float4 acc[2][4];
#pragma unroll
    for (int i = 0; i < 2; i++)
#pragma unroll
        for (int j = 0; j < 4; j++) acc[i][j] = make_float4(0.f, 0.f, 0.f, 0.f);

    // prologue fetch k0=0
    {
        int r0 = bm + arow0, r1 = bm + arow1;
        rA0 = (r0 < M) ? *(const float4*)&A[(size_t)r0 * K + akq] : make_float4(0.f, 0.f, 0.f, 0.f);
        rA1 = (r1 < M) ? *(const float4*)&A[(size_t)r1 * K + akq] : make_float4(0.f, 0.f, 0.f, 0.f);
        rB  = *(const float4*)&B[(size_t)brow * N + bn + bcol];
    }
    As[0][arow0][akq + 0] = to_tf32(rA0.x); As[0][arow0][akq + 1] = to_tf32(rA0.y);
    As[0][arow0][akq + 2] = to_tf32(rA0.z); As[0][arow0][akq + 3] = to_tf32(rA0.w);
    As[0][arow1][akq + 0] = to_tf32(rA1.x); As[0][arow1][akq + 1] = to_tf32(rA1.y);
    As[0][arow1][akq + 2] = to_tf32(rA1.z); As[0][arow1][akq + 3] = to_tf32(rA1.w);
    Bs[0][brow][bcol + 0] = to_tf32(rB.x);  Bs[0][brow][bcol + 1] = to_tf32(rB.y);
    Bs[0][brow][bcol + 2] = to_tf32(rB.z);  Bs[0][brow][bcol + 3] = to_tf32(rB.w);
    __syncthreads();

    int nk = K >> 4;
    for (int kt = 0; kt < nk; kt++) {
        int cur = kt & 1;
        if (kt + 1 < nk) {
            int k0 = (kt + 1) << 4;
            int r0 = bm + arow0, r1 = bm + arow1;
            rA0 = (r0 < M) ? *(const float4*)&A[(size_t)r0 * K + k0 + akq] : make_float4(0.f, 0.f, 0.f, 0.f);
            rA1 = (r1 < M) ? *(const float4*)&A[(size_t)r1 * K + k0 + akq] : make_float4(0.f, 0.f, 0.f, 0.f);
            rB  = *(const float4*)&B[(size_t)(k0 + brow) * N + bn + bcol];
        }
#pragma unroll
        for (int kk = 0; kk < 16; kk += 8) {
            float a[2][4];
#pragma unroll
            for (int mi = 0; mi < 2; mi++) {
                int m0 = wm * 32 + mi * 16;
                a[mi][0] = As[cur][m0 + g][kk + tg];
                a[mi][1] = As[cur][m0 + g + 8][kk + tg];
                a[mi][2] = As[cur][m0 + g][kk + tg + 4];
                a[mi][3] = As[cur][m0 + g + 8][kk + tg + 4];
            }
            float b[4][2];
#pragma unroll
            for (int ni = 0; ni < 4; ni++) {
                int n0 = wn * 32 + ni * 8;
                b[ni][0] = Bs[cur][kk + tg][n0 + g];
                b[ni][1] = Bs[cur][kk + tg + 4][n0 + g];
            }
#pragma unroll
            for (int mi = 0; mi < 2; mi++)
#pragma unroll
                for (int ni = 0; ni < 4; ni++)
                    mma8(acc[mi][ni], a[mi][0], a[mi][1], a[mi][2], a[mi][3],
                         b[ni][0], b[ni][1]);
        }
        if (kt + 1 < nk) {
            int nxt = cur ^ 1;
            As[nxt][arow0][akq + 0] = to_tf32(rA0.x); As[nxt][arow0][akq + 1] = to_tf32(rA0.y);
            As[nxt][arow0][akq + 2] = to_tf32(rA0.z); As[nxt][arow0][akq + 3] = to_tf32(rA0.w);
            As[nxt][arow1][akq + 0] = to_tf32(rA1.x); As[nxt][arow1][akq + 1] = to_tf32(rA1.y);
            As[nxt][arow1][akq + 2] = to_tf32(rA1.z); As[nxt][arow1][akq + 3] = to_tf32(rA1.w);
            Bs[nxt][brow][bcol + 0] = to_tf32(rB.x);  Bs[nxt][brow][bcol + 1] = to_tf32(rB.y);
            Bs[nxt][brow][bcol + 2] = to_tf32(rB.z);  Bs[nxt][brow][bcol + 3] = to_tf32(rB.w);
        }
        __syncthreads();
    }

    // epilogue: c0=(g,2tg) c1=(g,2tg+1) c2=(g+8,2tg) c3=(g+8,2tg+1)
#pragma unroll
    for (int mi = 0; mi < 2; mi++) {
        int r0 = bm + wm * 32 + mi * 16 + g;
        int r1 = r0 + 8;
#pragma unroll
        for (int ni = 0; ni < 4; ni++) {
            int c = bn + wn * 32 + ni * 8 + 2 * tg;
            if (r0 < M) *(float2*)&C[(size_t)r0 * N + c] = make_float2(acc[mi][ni].x, acc[mi][ni].y);
            if (r1 < M) *(float2*)&C[(size_t)r1 * N + c] = make_float2(acc[mi][ni].z, acc[mi][ni].w);
        }
    }
}

// ---------------- GCN aggregate: h0 = relu(dis[n]*sum(dis[s]*xw[s]) + b) ----------------
__global__ void k_gcn(const float* __restrict__ xw, const int* __restrict__ ei,
                      const float* __restrict__ b) {
    int warp = (blockIdx.x * blockDim.x + threadIdx.x) >> 5;
    int lane = threadIdx.x & 31;
    if (warp >= NNODES) return;
    int n = warp;
    int beg = g_rowptr[n], end = g_rowptr[n + 1];
    int cnt = end - beg;
    const unsigned FULL = 0xffffffffu;
    float a0 = 0.f, a1 = 0.f;

    if (cnt <= 128) {
        int   c_s[4];
        float c_w[4];
#pragma unroll
        for (int j = 0; j < 4; j++) {
            int idx = beg + j * 32 + lane;
            c_s[j] = 0; c_w[j] = 0.f;
            if (idx < end) {
                int e = g_eid[idx];
                int s = esrc(e, ei);
                c_s[j] = s;
                c_w[j] = g_dis[s];
            }
        }
#pragma unroll
        for (int j = 0; j < 4; j++) {
            int nj = cnt - j * 32;
            if (nj > 0) {
                if (nj > 32) nj = 32;
                int sj = c_s[j]; float wj = c_w[j];
                for (int tt = 0; tt < nj; tt++) {
                    int s   = __shfl_sync(FULL, sj, tt);
                    float w = __shfl_sync(FULL, wj, tt);
                    float2 v = *(const float2*)&xw[(size_t)s * 64 + lane * 2];
                    a0 += w * v.x;
                    a1 += w * v.y;
                }
            }
        }
    } else {
        for (int idx = beg; idx < end; idx++) {
            int e = g_eid[idx];
            int s = esrc(e, ei);
            float w = g_dis[s];
            float2 v = *(const float2*)&xw[(size_t)s * 64 + lane * 2];
            a0 += w * v.x;
            a1 += w * v.y;
        }
    }
    float dn = g_dis[n];
    float o0 = dn * a0 + b[lane * 2];
    float o1 = dn * a1 + b[lane * 2 + 1];
    g_h0[n * 64 + lane * 2]     = fmaxf(o0, 0.f);
    g_h0[n * 64 + lane * 2 + 1] = fmaxf(o1, 0.f);
}

// ---------------- attention pre: als/ald [N,4] from xw [N,256] ----------------
__global__ void k_attn(const float* __restrict__ xw, const float* __restrict__ asrc,
                       const float* __restrict__ adst,
                       float* __restrict__ als, float* __restrict__ ald) {
    int warp = (blockIdx.x * blockDim.x + threadIdx.x) >> 5;
    int lane = threadIdx.x & 31;
    if (warp >= NNODES) return;
    int n = warp;
    int c = lane * 8;
    const float4* xr = (const float4*)&xw[(size_t)n * 256 + c];
    const float4* sr = (const float4*)&asrc[c];
    const float4* dr = (const float4*)&adst[c];
    float4 xa = xr[0], xb = xr[1];
    float4 sa = sr[0], sb = sr[1];
    float4 da = dr[0], db = dr[1];
    float ps = xa.x * sa.x + xa.y * sa.y + xa.z * sa.z + xa.w * sa.w +
               xb.x * sb.x + xb.y * sb.y + xb.z * sb.z + xb.w * sb.w;
    float pd = xa.x * da.x + xa.y * da.y + xa.z * da.z + xa.w * da.w +
               xb.x * db.x + xb.y * db.y + xb.z * db.z + xb.w * db.w;
#pragma unroll
    for (int off = 4; off; off >>= 1) {
        ps += __shfl_xor_sync(0xffffffffu, ps, off);
        pd += __shfl_xor_sync(0xffffffffu, pd, off);
    }
    if ((lane & 7) == 0) {
        int h = lane >> 3;
        als[n * 4 + h] = ps;
        ald[n * 4 + h] = pd;
    }
}

// ---------------- GAT aggregate (softmax + weighted sum), one warp per dst node ----
// mode 0: concat (out 256) + relu; mode 1: head-mean (out 64) + relu; mode 2: head-mean
__global__ void k_gat(const float* __restrict__ xw, const int* __restrict__ ei,
                      const float* __restrict__ bias, float* __restrict__ alpha_out,
                      float* __restrict__ hout, int mode,
                      const float* __restrict__ als, const float* __restrict__ ald_g) {
    int warp = (blockIdx.x * blockDim.x + threadIdx.x) >> 5;
    int lane = threadIdx.x & 31;
    if (warp >= NNODES) return;
    int n = warp;
    int beg = g_rowptr[n], end = g_rowptr[n + 1];
    int cnt = end - beg;
    float4 ad = *(const float4*)&ald_g[n * 4];
    const unsigned FULL = 0xffffffffu;
    int head = lane >> 3;
    float4 accA = make_float4(0.f, 0.f, 0.f, 0.f);
    float4 accB = make_float4(0.f, 0.f, 0.f, 0.f);
    float i0, i1, i2, i3;

    if (cnt <= 128) {
        // ---- fast path: register-cached logits, exp computed once per edge ----
        int    c_src[4], c_e[4];
        float4 c_lg[4];
        float m0 = -1e30f, m1 = -1e30f, m2 = -1e30f, m3 = -1e30f;
#pragma unroll
        for (int j = 0; j < 4; j++) {
            int idx = beg + j * 32 + lane;
            c_src[j] = -1; c_e[j] = 0;
            c_lg[j] = make_float4(0.f, 0.f, 0.f, 0.f);
            if (idx < end) {
                int e = g_eid[idx];
                int s = esrc(e, ei);
                c_e[j] = e; c_src[j] = s;
                float4 as4 = *(const float4*)&als[s * 4];
                float4 lg = make_float4(lrelu(as4.x + ad.x), lrelu(as4.y + ad.y),
                                        lrelu(as4.z + ad.z), lrelu(as4.w + ad.w));
                c_lg[j] = lg;
                m0 = fmaxf(m0, lg.x); m1 = fmaxf(m1, lg.y);
                m2 = fmaxf(m2, lg.z); m3 = fmaxf(m3, lg.w);
            }
        }
#pragma unroll
        for (int off = 16; off; off >>= 1) {
            m0 = fmaxf(m0, __shfl_xor_sync(FULL, m0, off));
            m1 = fmaxf(m1, __shfl_xor_sync(FULL, m1, off));
            m2 = fmaxf(m2, __shfl_xor_sync(FULL, m2, off));
            m3 = fmaxf(m3, __shfl_xor_sync(FULL, m3, off));
        }
        float s0 = 0.f, s1 = 0.f, s2 = 0.f, s3 = 0.f;
#pragma unroll
        for (int j = 0; j < 4; j++) {
            if (c_src[j] >= 0) {
                float4 lg = c_lg[j];
                lg.x = expf(lg.x - m0); lg.y = expf(lg.y - m1);
                lg.z = expf(lg.z - m2); lg.w = expf(lg.w - m3);
                c_lg[j] = lg;
                s0 += lg.x; s1 += lg.y; s2 += lg.z; s3 += lg.w;
            }
        }
#pragma unroll
        for (int off = 16; off; off >>= 1) {
            s0 += __shfl_xor_sync(FULL, s0, off);
            s1 += __shfl_xor_sync(FULL, s1, off);
            s2 += __shfl_xor_sync(FULL, s2, off);
            s3 += __shfl_xor_sync(FULL, s3, off);
        }
        i0 = 1.f / (s0 + 1e-16f); i1 = 1.f / (s1 + 1e-16f);
        i2 = 1.f / (s2 + 1e-16f); i3 = 1.f / (s3 + 1e-16f);
        // write alphas (coalesced by owning lane)
#pragma unroll
        for (int j = 0; j < 4; j++) {
            if (c_src[j] >= 0) {
                float4 lg = c_lg[j];
                *(float4*)&alpha_out[(size_t)c_e[j] * 4] =
                    make_float4(lg.x * i0, lg.y * i1, lg.z * i2, lg.w * i3);
            }
        }
        // aggregate: broadcast alpha via shfl
#pragma unroll
        for (int j = 0; j < 4; j++) {
            int nj = cnt - j * 32;
            if (nj > 0) {
                if (nj > 32) nj = 32;
                int sj = c_src[j]; float4 lg = c_lg[j];
                for (int tt = 0; tt < nj; tt++) {
                    int s    = __shfl_sync(FULL, sj, tt);
                    float e0 = __shfl_sync(FULL, lg.x, tt);
                    float e1 = __shfl_sync(FULL, lg.y, tt);
                    float e2 = __shfl_sync(FULL, lg.z, tt);
                    float e3 = __shfl_sync(FULL, lg.w, tt);
                    float myA = (head == 0) ? e0 * i0 : (head == 1) ? e1 * i1
                              : (head == 2) ? e2 * i2 : e3 * i3;
                    const float4* xr = (const float4*)&xw[(size_t)s * 256 + lane * 8];
                    float4 xa = xr[0], xb = xr[1];
                    accA.x += myA * xa.x; accA.y += myA * xa.y;
                    accA.z += myA * xa.z; accA.w += myA * xa.w;
                    accB.x += myA * xb.x; accB.y += myA * xb.y;
                    accB.z += myA * xb.z; accB.w += myA * xb.w;
                }
            }
        }
    } else {
        // ---- fallback: 3-pass gather (deg > 128) ----
        float m0 = -1e30f, m1 = -1e30f, m2 = -1e30f, m3 = -1e30f;
        for (int idx = beg + lane; idx < end; idx += 32) {
            int e = g_eid[idx];
            int s = esrc(e, ei);
            float4 as4 = *(const float4*)&als[s * 4];
            m0 = fmaxf(m0, lrelu(as4.x + ad.x));
            m1 = fmaxf(m1, lrelu(as4.y + ad.y));
            m2 = fmaxf(m2, lrelu(as4.z + ad.z));
            m3 = fmaxf(m3, lrelu(as4.w + ad.w));
        }
#pragma unroll
        for (int off = 16; off; off >>= 1) {
            m0 = fmaxf(m0, __shfl_xor_sync(FULL, m0, off));
            m1 = fmaxf(m1, __shfl_xor_sync(FULL, m1, off));
            m2 = fmaxf(m2, __shfl_xor_sync(FULL, m2, off));
            m3 = fmaxf(m3, __shfl_xor_sync(FULL, m3, off));
        }
        float s0 = 0.f, s1 = 0.f, s2 = 0.f, s3 = 0.f;
        for (int idx = beg + lane; idx < end; idx += 32) {
            int e = g_eid[idx];
            int s = esrc(e, ei);
            float4 as4 = *(const float4*)&als[s * 4];
            s0 += expf(lrelu(as4.x + ad.x) - m0);
            s1 += expf(lrelu(as4.y + ad.y) - m1);
            s2 += expf(lrelu(as4.z + ad.z) - m2);
            s3 += expf(lrelu(as4.w + ad.w) - m3);
        }
#pragma unroll
        for (int off = 16; off; off >>= 1) {
            s0 += __shfl_xor_sync(FULL, s0, off);
            s1 += __shfl_xor_sync(FULL, s1, off);
            s2 += __shfl_xor_sync(FULL, s2, off);
            s3 += __shfl_xor_sync(FULL, s3, off);
        }
        i0 = 1.f / (s0 + 1e-16f); i1 = 1.f / (s1 + 1e-16f);
        i2 = 1.f / (s2 + 1e-16f); i3 = 1.f / (s3 + 1e-16f);
        for (int idx = beg; idx < end; idx++) {
            int e = g_eid[idx];
            int s = esrc(e, ei);
            float4 as4 = *(const float4*)&als[s * 4];
            float a0 = expf(lrelu(as4.x + ad.x) - m0) * i0;
            float a1 = expf(lrelu(as4.y + ad.y) - m1) * i1;
            float a2 = expf(lrelu(as4.z + ad.z) - m2) * i2;
            float a3 = expf(lrelu(as4.w + ad.w) - m3) * i3;
            if (lane < 4) {
                float av = (lane == 0) ? a0 : (lane == 1) ? a1 : (lane == 2) ? a2 : a3;
                alpha_out[(size_t)e * 4 + lane] = av;
            }
            float myA = (head == 0) ? a0 : (head == 1) ? a1 : (head == 2) ? a2 : a3;
            const float4* xr = (const float4*)&xw[(size_t)s * 256 + lane * 8];
            float4 xa = xr[0], xb = xr[1];
            accA.x += myA * xa.x; accA.y += myA * xa.y;
            accA.z += myA * xa.z; accA.w += myA * xa.w;
            accB.x += myA * xb.x; accB.y += myA * xb.y;
            accB.z += myA * xb.z; accB.w += myA * xb.w;
        }
    }

    // ---- epilogue ----
    if (mode == 0) {
        int c = lane * 8;
        float4 bA = *(const float4*)&bias[c];
        float4 bB = *(const float4*)&bias[c + 4];
        float4 oA = make_float4(fmaxf(accA.x + bA.x, 0.f), fmaxf(accA.y + bA.y, 0.f),
                                fmaxf(accA.z + bA.z, 0.f), fmaxf(accA.w + bA.w, 0.f));
        float4 oB = make_float4(fmaxf(accB.x + bB.x, 0.f), fmaxf(accB.y + bB.y, 0.f),
                                fmaxf(accB.z + bB.z, 0.f), fmaxf(accB.w + bB.w, 0.f));
        *(float4*)&hout[(size_t)n * 256 + c] = oA;
        *(float4*)&hout[(size_t)n * 256 + c + 4] = oB;
    } else {
        // sum across heads: lanes differing in bits 3,4 hold the other heads' copies
#pragma unroll
        for (int off = 8; off <= 16; off <<= 1) {
            accA.x += __shfl_xor_sync(FULL, accA.x, off);
            accA.y += __shfl_xor_sync(FULL, accA.y, off);
            accA.z += __shfl_xor_sync(FULL, accA.z, off);
            accA.w += __shfl_xor_sync(FULL, accA.w, off);
            accB.x += __shfl_xor_sync(FULL, accB.x, off);
            accB.y += __shfl_xor_sync(FULL, accB.y, off);
            accB.z += __shfl_xor_sync(FULL, accB.z, off);
            accB.w += __shfl_xor_sync(FULL, accB.w, off);
        }
        if (lane < 8) {
            int c = lane * 8;
            float4 bA = *(const float4*)&bias[c];
            float4 bB = *(const float4*)&bias[c + 4];
            float4 oA = make_float4(accA.x * 0.25f + bA.x, accA.y * 0.25f + bA.y,
                                    accA.z * 0.25f + bA.z, accA.w * 0.25f + bA.w);
            float4 oB = make_float4(accB.x * 0.25f + bB.x, accB.y * 0.25f + bB.y,
                                    accB.z * 0.25f + bB.z, accB.w * 0.25f + bB.w);
            if (mode == 1) {
                oA = make_float4(fmaxf(oA.x, 0.f), fmaxf(oA.y, 0.f), fmaxf(oA.z, 0.f), fmaxf(oA.w, 0.f));
                oB = make_float4(fmaxf(oB.x, 0.f), fmaxf(oB.y, 0.f), fmaxf(oB.z, 0.f), fmaxf(oB.w, 0.f));
            }
            *(float4*)&hout[(size_t)n * 64 + c] = oA;
            *(float4*)&hout[(size_t)n * 64 + c + 4] = oB;
        }
    }
}

// ---------------- host ----------------
extern "C" void kernel_launch(void* const* d_in, const int* in_sizes, int n_in,
                              void* d_out, int out_size) {
    const float* x      = (const float*)d_in[0];
    const int*   ei     = (const int*)d_in[1];
    const float* gcn_W  = (const float*)d_in[2];
    const float* gcn_b  = (const float*)d_in[3];
    const float* g1_W   = (const float*)d_in[4];
    const float* g1_as  = (const float*)d_in[5];
    const float* g1_ad  = (const float*)d_in[6];
    const float* g1_b   = (const float*)d_in[7];
    const float* g2_W   = (const float*)d_in[8];
    const float* g2_as  = (const float*)d_in[9];
    const float* g2_ad  = (const float*)d_in[10];
    const float* g2_b   = (const float*)d_in[11];
    const float* m_W    = (const float*)d_in[12];
    const float* m_as   = (const float*)d_in[13];
    const float* m_ad   = (const float*)d_in[14];
    const float* m_b    = (const float*)d_in[15];
    const float* s_W    = (const float*)d_in[16];
    const float* s_as   = (const float*)d_in[17];
    const float* s_ad   = (const float*)d_in[18];
    const float* s_b    = (const float*)d_in[19];

    float* out    = (float*)d_out;
    float* z_mean = out;
    float* z_std  = out + (size_t)NNODES * 64;
    float* a1     = out + (size_t)NNODES * 128;
    float* a2     = a1 + (size_t)EPRIME * 4;
    float* am     = a2 + (size_t)EPRIME * 4;
    float* as     = am + (size_t)EPRIME * 4;

    float *p_xw, *p_xw2, *p_h0, *p_h1, *p_h2;
    float *p_als, *p_ald, *p_als2, *p_ald2;
    int   *p_deg;
    cudaGetSymbolAddress((void**)&p_xw,  g_xw);
    cudaGetSymbolAddress((void**)&p_xw2, g_xw2);
    cudaGetSymbolAddress((void**)&p_h0,  g_h0);
    cudaGetSymbolAddress((void**)&p_h1,  g_h1);
    cudaGetSymbolAddress((void**)&p_h2,  g_h2);
    cudaGetSymbolAddress((void**)&p_als, g_als);
    cudaGetSymbolAddress((void**)&p_ald, g_ald);
    cudaGetSymbolAddress((void**)&p_als2, g_als2);
    cudaGetSymbolAddress((void**)&p_ald2, g_ald2);
    cudaGetSymbolAddress((void**)&p_deg, g_deg);

    const int TB = 256;
    int edgeBlocks = (EPRIME + TB - 1) / TB;             // elementwise over edges
    int warpBlocks = (NNODES * 32 + TB - 1) / TB;        // one warp per node

    dim3 g64(1, (NNODES + 127) / 128), g256(4, (NNODES + 127) / 128);

    // ---- fork: GCN GEMM on s2 (independent of CSR build) ----
    cudaEventRecord(g_ev0, 0);
    cudaStreamWaitEvent(g_s2, g_ev0, 0);
    k_sgemm<<<g64, 256, 0, g_s2>>>(x, gcn_W, p_xw, NNODES, 64, 128);
    cudaEventRecord(g_ev1, g_s2);

    // ---- CSR build on default stream (runs concurrently) ----
    cudaMemsetAsync(p_deg, 0, NNODES * sizeof(int));
    k_count<<<edgeBlocks, TB>>>(ei);
    k_scan<<<1, 1024>>>();
    k_scatter<<<edgeBlocks, TB>>>(ei);

    // join: k_gcn needs both CSR and xw
    cudaStreamWaitEvent(0, g_ev1, 0);
    k_gcn<<<warpBlocks, TB>>>(p_xw, ei, gcn_b);

    // GAT1 (concat + relu)
    k_sgemm<<<g256, 256>>>(p_h0, g1_W, p_xw, NNODES, 256, 64);
    k_attn<<<warpBlocks, TB>>>(p_xw, g1_as, g1_ad, p_als, p_ald);
    k_gat<<<warpBlocks, TB>>>(p_xw, ei, g1_b, a1, p_h1, 0, p_als, p_ald);

    // GAT2 (mean + relu)
    k_sgemm<<<g256, 256>>>(p_h1, g2_W, p_xw, NNODES, 256, 256);
    k_attn<<<warpBlocks, TB>>>(p_xw, g2_as, g2_ad, p_als, p_ald);
    k_gat<<<warpBlocks, TB>>>(p_xw, ei, g2_b, a2, p_h2, 1, p_als, p_ald);

    // ---- fork: std chain on s2, mean chain on default stream ----
    cudaEventRecord(g_ev2, 0);
    cudaStreamWaitEvent(g_s2, g_ev2, 0);

    // std head (mean, no relu) on s2, private scratch
    k_sgemm<<<g256, 256, 0, g_s2>>>(p_h2, s_W, p_xw2, NNODES, 256, 64);
    k_attn<<<warpBlocks, TB, 0, g_s2>>>(p_xw2, s_as, s_ad, p_als2, p_ald2);
    k_gat<<<warpBlocks, TB, 0, g_s2>>>(p_xw2, ei, s_b, as, z_std, 2, p_als2, p_ald2);
    cudaEventRecord(g_ev3, g_s2);

    // mean head (mean, no relu) on default stream
    k_sgemm<<<g256, 256>>>(p_h2, m_W, p_xw, NNODES, 256, 64);
    k_attn<<<warpBlocks, TB>>>(p_xw, m_as, m_ad, p_als, p_ald);
    k_gat<<<warpBlocks, TB>>>(p_xw, ei, m_b, am, z_mean, 2, p_als, p_ald);

    // join
    cudaStreamWaitEvent(0, g_ev3, 0);
}

// round 12
// speedup vs baseline: 1.8681x; 1.0651x over previous
#include <cuda_runtime.h>

#define NNODES 20000
#define NEDGES 320000
#define EPRIME (NNODES + NEDGES)   // 340000 (edges + self loops)

// ---------------- scratch (static device globals; no allocation) ----------------
__device__ int   g_deg[NNODES];
__device__ int   g_rowptr[NNODES + 1];
__device__ int   g_cursor[NNODES];
__device__ int   g_eid[EPRIME];
__device__ int   g_src[EPRIME];         // src node per CSR slot (kills eid->ei indirection)
__device__ float g_dis[NNODES];
__device__ float g_xw[NNODES * 256];
__device__ float g_xw2[NNODES * 256];   // second scratch for parallel std chain
__device__ float g_h0[NNODES * 64];
__device__ float g_h1[NNODES * 256];
__device__ float g_h2[NNODES * 64];
__device__ float g_als[NNODES * 4];
__device__ float g_ald[NNODES * 4];
__device__ float g_als2[NNODES * 4];
__device__ float g_ald2[NNODES * 4];

// ---------------- streams/events for graph-capture fork/join ----------------
static cudaStream_t g_s2;
static cudaEvent_t g_ev0, g_ev1, g_ev2, g_ev3;
namespace {
struct StreamInit {
    StreamInit() {
        cudaStreamCreateWithFlags(&g_s2, cudaStreamNonBlocking);
        cudaEventCreateWithFlags(&g_ev0, cudaEventDisableTiming);
        cudaEventCreateWithFlags(&g_ev1, cudaEventDisableTiming);
        cudaEventCreateWithFlags(&g_ev2, cudaEventDisableTiming);
        cudaEventCreateWithFlags(&g_ev3, cudaEventDisableTiming);
    }
};
StreamInit s_streamInit;
}

__device__ __forceinline__ float lrelu(float v) { return v > 0.f ? v : 0.2f * v; }
__device__ __forceinline__ int esrc(int e, const int* __restrict__ ei) {
    return (e < NEDGES) ? ei[e] : (e - NEDGES);
}
__device__ __forceinline__ int edst(int e, const int* __restrict__ ei) {
    return (e < NEDGES) ? ei[NEDGES + e] : (e - NEDGES);
}

// ---------------- CSR build ----------------
__global__ void k_count(const int* __restrict__ ei) {
    int e = blockIdx.x * blockDim.x + threadIdx.x;
    if (e < EPRIME) atomicAdd(&g_deg[edst(e, ei)], 1);
}

// single block, 1024 threads: exclusive scan of deg -> rowptr, cursor; also dis
__global__ void k_scan() {
    const int CH = (NNODES + 1023) / 1024;  // 20
    __shared__ int sums[1024];
    int t = threadIdx.x;
    int base = t * CH;
    int local[CH];
    int s = 0;
#pragma unroll
    for (int i = 0; i < CH; i++) {
        int idx = base + i;
        int v = (idx < NNODES) ? g_deg[idx] : 0;
        if (idx < NNODES) g_dis[idx] = rsqrtf((float)v);  // deg >= 1 (self loops)
        local[i] = s;
        s += v;
    }
    sums[t] = s;
    __syncthreads();
    for (int off = 1; off < 1024; off <<= 1) {
        int v = (t >= off) ? sums[t - off] : 0;
        __syncthreads();
        sums[t] += v;
        __syncthreads();
    }
    int offset = (t > 0) ? sums[t - 1] : 0;
#pragma unroll
    for (int i = 0; i < CH; i++) {
        int idx = base + i;
        if (idx < NNODES) {
            int r = offset + local[i];
            g_rowptr[idx] = r;
            g_cursor[idx] = r;
        }
    }
    if (t == 1023) g_rowptr[NNODES] = sums[1023];
}

__global__ void k_scatter(const int* __restrict__ ei) {
    int e = blockIdx.x * blockDim.x + threadIdx.x;
    if (e < EPRIME) {
        int s = esrc(e, ei);
        int pos = atomicAdd(&g_cursor[edst(e, ei)], 1);
        g_eid[pos] = e;
        g_src[pos] = s;
    }
}

// ---------------- tf32 tensor-core helpers ----------------
__device__ __forceinline__ float to_tf32(float x) {
    unsigned u;
    asm("cvt.rna.tf32.f32 %0, %1;" : "=r"(u) : "f"(x));
    return __uint_as_float(u);
}

__device__ __forceinline__ void mma8(float4& d, float a0, float a1, float a2, float a3,
                                     float b0, float b1) {
    asm volatile(
        "mma.sync.aligned.m16n8k8.row.col.f32.tf32.tf32.f32 "
        "{%0,%1,%2,%3}, {%4,%5,%6,%7}, {%8,%9}, {%0,%1,%2,%3};"
        : "+f"(d.x), "+f"(d.y), "+f"(d.z), "+f"(d.w)
        : "r"(__float_as_uint(a0)), "r"(__float_as_uint(a1)),
          "r"(__float_as_uint(a2)), "r"(__float_as_uint(a3)),
          "r"(__float_as_uint(b0)), "r"(__float_as_uint(b1)));
}

// ---------------- tf32 tiled GEMM: C[M,N] = A[M,K] @ B[K,N] ----------------
// 128x64 CTA tile, BK=16, 256 threads = 8 warps (4x2), warp tile 32x32.
// K % 16 == 0, N % 64 == 0. Inputs rounded to tf32 at smem fill; fp32 accum.
// Optional fused attention epilogue (als/ald dot-products) for N=256 GAT GEMMs:
// each CTA's 64-column range is exactly one head (h = bn>>6), so als[n,h] =
// sum over CTA cols of acc*asrc reduces within the CTA (quad shfl + smem), no atomics.
__global__ __launch_bounds__(256) void k_sgemm(const float* __restrict__ A,
                                               const float* __restrict__ B,
                                               float* __restrict__ C,
                                               int M, int N, int K,
                                               const float* __restrict__ asrc,
                                               const float* __restrict__ adst,
                                               float* __restrict__ als_out,
                                               float* __restrict__ ald_out) {
    __shared__ float As[2][128][20];  // [m][k], stride 20 (=4 mod 32): frag loads conflict-free
    __shared__ float Bs[2][16][72];   // [k][n], stride 72 (=8 mod 32): frag loads conflict-free
    int t = threadIdx.x;
    int bm = blockIdx.y * 128, bn = blockIdx.x * 64;
    int warp = t >> 5, lane = t & 31;
    int wm = warp & 3, wn = warp >> 2;      // 4 warps along M, 2 along N
    int g = lane >> 2, tg = lane & 3;

    int arow0 = t >> 2, arow1 = arow0 + 64, akq = (t & 3) * 4;  // A: 2 float4/thread
    int brow = t >> 4, bcol = (t & 15) * 4;                      // B: 1 float4/thread

    float4 rA0, rA1, rB;
    float4 acc[2][4];
#pragma unroll
    for (int i = 0; i < 2; i++)
#pragma unroll
        for (int j = 0; j < 4; j++) acc[i][j] = make_float4(0.f, 0.f, 0.f, 0.f);

    // prologue fetch k0=0
    {
        int r0 = bm + arow0, r1 = bm + arow1;
        rA0 = (r0 < M) ? *(const float4*)&A[(size_t)r0 * K + akq] : make_float4(0.f, 0.f, 0.f, 0.f);
        rA1 = (r1 < M) ? *(const float4*)&A[(size_t)r1 * K + akq] : make_float4(0.f, 0.f, 0.f, 0.f);
        rB  = *(const float4*)&B[(size_t)brow * N + bn + bcol];
    }
    As[0][arow0][akq + 0] = to_tf32(rA0.x); As[0][arow0][akq + 1] = to_tf32(rA0.y);
    As[0][arow0][akq + 2] = to_tf32(rA0.z); As[0][arow0][akq + 3] = to_tf32(rA0.w);
    As[0][arow1][akq + 0] = to_tf32(rA1.x); As[0][arow1][akq + 1] = to_tf32(rA1.y);
    As[0][arow1][akq + 2] = to_tf32(rA1.z); As[0][arow1][akq + 3] = to_tf32(rA1.w);
    Bs[0][brow][bcol + 0] = to_tf32(rB.x);  Bs[0][brow][bcol + 1] = to_tf32(rB.y);
    Bs[0][brow][bcol + 2] = to_tf32(rB.z);  Bs[0][brow][bcol + 3] = to_tf32(rB.w);
    __syncthreads();

    int nk = K >> 4;
    for (int kt = 0; kt < nk; kt++) {
        int cur = kt & 1;
        if (kt + 1 < nk) {
            int k0 = (kt + 1) << 4;
            int r0 = bm + arow0, r1 = bm + arow1;
            rA0 = (r0 < M) ? *(const float4*)&A[(size_t)r0 * K + k0 + akq] : make_float4(0.f, 0.f, 0.f, 0.f);
            rA1 = (r1 < M) ? *(const float4*)&A[(size_t)r1 * K + k0 + akq] : make_float4(0.f, 0.f, 0.f, 0.f);
            rB  = *(const float4*)&B[(size_t)(k0 + brow) * N + bn + bcol];
        }
#pragma unroll
        for (int kk = 0; kk < 16; kk += 8) {
            float a[2][4];
#pragma unroll
            for (int mi = 0; mi < 2; mi++) {
                int m0 = wm * 32 + mi * 16;
                a[mi][0] = As[cur][m0 + g][kk + tg];
                a[mi][1] = As[cur][m0 + g + 8][kk + tg];
                a[mi][2] = As[cur][m0 + g][kk + tg + 4];
                a[mi][3] = As[cur][m0 + g + 8][kk + tg + 4];
            }
            float b[4][2];
#pragma unroll
            for (int ni = 0; ni < 4; ni++) {
                int n0 = wn * 32 + ni * 8;
                b[ni][0] = Bs[cur][kk + tg][n0 + g];
                b[ni][1] = Bs[cur][kk + tg + 4][n0 + g];
            }
#pragma unroll
            for (int mi = 0; mi < 2; mi++)
#pragma unroll
                for (int ni = 0; ni < 4; ni++)
                    mma8(acc[mi][ni], a[mi][0], a[mi][1], a[mi][2], a[mi][3],
                         b[ni][0], b[ni][1]);
        }
        if (kt + 1 < nk) {
            int nxt = cur ^ 1;
            As[nxt][arow0][akq + 0] = to_tf32(rA0.x); As[nxt][arow0][akq + 1] = to_tf32(rA0.y);
            As[nxt][arow0][akq + 2] = to_tf32(rA0.z); As[nxt][arow0][akq + 3] = to_tf32(rA0.w);
            As[nxt][arow1][akq + 0] = to_tf32(rA1.x); As[nxt][arow1][akq + 1] = to_tf32(rA1.y);
            As[nxt][arow1][akq + 2] = to_tf32(rA1.z); As[nxt][arow1][akq + 3] = to_tf32(rA1.w);
            Bs[nxt][brow][bcol + 0] = to_tf32(rB.x);  Bs[nxt][brow][bcol + 1] = to_tf32(rB.y);
            Bs[nxt][brow][bcol + 2] = to_tf32(rB.z);  Bs[nxt][brow][bcol + 3] = to_tf32(rB.w);
        }
        __syncthreads();
    }

    // epilogue: c0=(g,2tg) c1=(g,2tg+1) c2=(g+8,2tg) c3=(g+8,2tg+1)
#pragma unroll
    for (int mi = 0; mi < 2; mi++) {
        int r0 = bm + wm * 32 + mi * 16 + g;
        int r1 = r0 + 8;
#pragma unroll
        for (int ni = 0; ni < 4; ni++) {
            int c = bn + wn * 32 + ni * 8 + 2 * tg;
            if (r0 < M) *(float2*)&C[(size_t)r0 * N + c] = make_float2(acc[mi][ni].x, acc[mi][ni].y);
            if (r1 < M) *(float2*)&C[(size_t)r1 * N + c] = make_float2(acc[mi][ni].z, acc[mi][ni].w);
        }
    }

    // ---- fused attention dot-products (N=256 GAT GEMMs only) ----
    if (als_out) {
        float pa[2][2] = {{0.f, 0.f}, {0.f, 0.f}};
        float pd[2][2] = {{0.f, 0.f}, {0.f, 0.f}};
#pragma unroll
        for (int mi = 0; mi < 2; mi++)
#pragma unroll
            for (int ni = 0; ni < 4; ni++) {
                int c = bn + wn * 32 + ni * 8 + 2 * tg;  // flat [4,64] index == global col
                float s0 = asrc[c], s1 = asrc[c + 1];
                float d0 = adst[c], d1 = adst[c + 1];
                float4 v = acc[mi][ni];
                pa[mi][0] += v.x * s0 + v.y * s1;
                pa[mi][1] += v.z * s0 + v.w * s1;
                pd[mi][0] += v.x * d0 + v.y * d1;
                pd[mi][1] += v.z * d0 + v.w * d1;
            }
        // quad reduce over tg (lanes 4g..4g+3)
#pragma unroll
        for (int m = 1; m <= 2; m <<= 1) {
#pragma unroll
            for (int mi = 0; mi < 2; mi++) {
                pa[mi][0] += __shfl_xor_sync(0xffffffffu, pa[mi][0], m);
                pa[mi][1] += __shfl_xor_sync(0xffffffffu, pa[mi][1], m);
                pd[mi][0] += __shfl_xor_sync(0xffffffffu, pd[mi][0], m);
                pd[mi][1] += __shfl_xor_sync(0xffffffffu, pd[mi][1], m);
            }
        }
        // cross-warp (wn) combine through smem (safe to reuse As: all mainloop
        // smem reads are behind the final __syncthreads)
        float* sbuf = &As[0][0][0];  // [0..255]=als partials (wn,row), [256..511]=ald
        if (tg == 0) {
#pragma unroll
            for (int mi = 0; mi < 2; mi++) {
                int rl = wm * 32 + mi * 16 + g;
                sbuf[wn * 128 + rl]       = pa[mi][0];
                sbuf[wn * 128 + rl + 8]   = pa[mi][1];
                sbuf[256 + wn * 128 + rl]     = pd[mi][0];
                sbuf[256 + wn * 128 + rl + 8] = pd[mi][1];
            }
        }
        __syncthreads();
        if (t < 128) {
            int row = bm + t;
            if (row < M) {
                int h = bn >> 6;
                als_out[row * 4 + h] = sbuf[t] + sbuf[128 + t];
                ald_out[row * 4 + h] = sbuf[256 + t] + sbuf[384 + t];
            }
        }
    }
}

// ---------------- GCN aggregate: h0 = relu(dis[n]*sum(dis[s]*xw[s]) + b) ----------------
__global__ void k_gcn(const float* __restrict__ xw, const float* __restrict__ b) {
    int warp = (blockIdx.x * blockDim.x + threadIdx.x) >> 5;
    int lane = threadIdx.x & 31;
    if (warp >= NNODES) return;
    int n = warp;
    int beg = g_rowptr[n], end = g_rowptr[n + 1];
    int cnt = end - beg;
    const unsigned FULL = 0xffffffffu;
    float a0 = 0.f, a1 = 0.f;

    if (cnt <= 128) {
        int   c_s[4];
        float c_w[4];
#pragma unroll
        for (int j = 0; j < 4; j++) {
            int idx = beg + j * 32 + lane;
            c_s[j] = 0; c_w[j] = 0.f;
            if (idx < end) {
                int s = g_src[idx];
                c_s[j] = s;
                c_w[j] = g_dis[s];
            }
        }
#pragma unroll
        for (int j = 0; j < 4; j++) {
            int nj = cnt - j * 32;
            if (nj > 0) {
                if (nj > 32) nj = 32;
                int sj = c_s[j]; float wj = c_w[j];
                for (int tt = 0; tt < nj; tt++) {
                    int s   = __shfl_sync(FULL, sj, tt);
                    float w = __shfl_sync(FULL, wj, tt);
                    float2 v = *(const float2*)&xw[(size_t)s * 64 + lane * 2];
                    a0 += w * v.x;
                    a1 += w * v.y;
                }
            }
        }
    } else {
        for (int idx = beg; idx < end; idx++) {
            int s = g_src[idx];
            float w = g_dis[s];
            float2 v = *(const float2*)&xw[(size_t)s * 64 + lane * 2];
            a0 += w * v.x;
            a1 += w * v.y;
        }
    }
    float dn = g_dis[n];
    float o0 = dn * a0 + b[lane * 2];
    float o1 = dn * a1 + b[lane * 2 + 1];
    g_h0[n * 64 + lane * 2]     = fmaxf(o0, 0.f);
    g_h0[n * 64 + lane * 2 + 1] = fmaxf(o1, 0.f);
}

// ---------------- GAT aggregate (softmax + weighted sum), one warp per dst node ----
// mode 0: concat (out 256) + relu; mode 1: head-mean (out 64) + relu; mode 2: head-mean
__global__ void k_gat(const float* __restrict__ xw, const float* __restrict__ bias,
                      float* __restrict__ alpha_out, float* __restrict__ hout, int mode,
                      const float* __restrict__ als, const float* __restrict__ ald_g) {
    int warp = (blockIdx.x * blockDim.x + threadIdx.x) >> 5;
    int lane = threadIdx.x & 31;
    if (warp >= NNODES) return;
    int n = warp;
    int beg = g_rowptr[n], end = g_rowptr[n + 1];
    int cnt = end - beg;
    float4 ad = *(const float4*)&ald_g[n * 4];
    const unsigned FULL = 0xffffffffu;
    int head = lane >> 3;
    float4 accA = make_float4(0.f, 0.f, 0.f, 0.f);
    float4 accB = make_float4(0.f, 0.f, 0.f, 0.f);
    float i0, i1, i2, i3;

    if (cnt <= 128) {
        // ---- fast path: register-cached logits, exp computed once per edge ----
        int    c_src[4], c_e[4];
        float4 c_lg[4];
        float m0 = -1e30f, m1 = -1e30f, m2 = -1e30f, m3 = -1e30f;
#pragma unroll
        for (int j = 0; j < 4; j++) {
            int idx = beg + j * 32 + lane;
            c_src[j] = -1; c_e[j] = 0;
            c_lg[j] = make_float4(0.f, 0.f, 0.f, 0.f);
            if (idx < end) {
                c_e[j] = g_eid[idx];
                int s = g_src[idx];
                c_src[j] = s;
                float4 as4 = *(const float4*)&als[s * 4];
                float4 lg = make_float4(lrelu(as4.x + ad.x), lrelu(as4.y + ad.y),
                                        lrelu(as4.z + ad.z), lrelu(as4.w + ad.w));
                c_lg[j] = lg;
                m0 = fmaxf(m0, lg.x); m1 = fmaxf(m1, lg.y);
                m2 = fmaxf(m2, lg.z); m3 = fmaxf(m3, lg.w);
            }
        }
#pragma unroll
        for (int off = 16; off; off >>= 1) {
            m0 = fmaxf(m0, __shfl_xor_sync(FULL, m0, off));
            m1 = fmaxf(m1, __shfl_xor_sync(FULL, m1, off));
            m2 = fmaxf(m2, __shfl_xor_sync(FULL, m2, off));
            m3 = fmaxf(m3, __shfl_xor_sync(FULL, m3, off));
        }
        float s0 = 0.f, s1 = 0.f, s2 = 0.f, s3 = 0.f;
#pragma unroll
        for (int j = 0; j < 4; j++) {
            if (c_src[j] >= 0) {
                float4 lg = c_lg[j];
                lg.x = expf(lg.x - m0); lg.y = expf(lg.y - m1);
                lg.z = expf(lg.z - m2); lg.w = expf(lg.w - m3);
                c_lg[j] = lg;
                s0 += lg.x; s1 += lg.y; s2 += lg.z; s3 += lg.w;
            }
        }
#pragma unroll
        for (int off = 16; off; off >>= 1) {
            s0 += __shfl_xor_sync(FULL, s0, off);
            s1 += __shfl_xor_sync(FULL, s1, off);
            s2 += __shfl_xor_sync(FULL, s2, off);
            s3 += __shfl_xor_sync(FULL, s3, off);
        }
        i0 = 1.f / (s0 + 1e-16f); i1 = 1.f / (s1 + 1e-16f);
        i2 = 1.f / (s2 + 1e-16f); i3 = 1.f / (s3 + 1e-16f);
        // write alphas (coalesced by owning lane)
#pragma unroll
        for (int j = 0; j < 4; j++) {
            if (c_src[j] >= 0) {
                float4 lg = c_lg[j];
                *(float4*)&alpha_out[(size_t)c_e[j] * 4] =
                    make_float4(lg.x * i0, lg.y * i1, lg.z * i2, lg.w * i3);
            }
        }
        // aggregate: broadcast alpha via shfl
#pragma unroll
        for (int j = 0; j < 4; j++) {
            int nj = cnt - j * 32;
            if (nj > 0) {
                if (nj > 32) nj = 32;
                int sj = c_src[j]; float4 lg = c_lg[j];
                for (int tt = 0; tt < nj; tt++) {
                    int s    = __shfl_sync(FULL, sj, tt);
                    float e0 = __shfl_sync(FULL, lg.x, tt);
                    float e1 = __shfl_sync(FULL, lg.y, tt);
                    float e2 = __shfl_sync(FULL, lg.z, tt);
                    float e3 = __shfl_sync(FULL, lg.w, tt);
                    float myA = (head == 0) ? e0 * i0 : (head == 1) ? e1 * i1
                              : (head == 2) ? e2 * i2 : e3 * i3;
                    const float4* xr = (const float4*)&xw[(size_t)s * 256 + lane * 8];
                    float4 xa = xr[0], xb = xr[1];
                    accA.x += myA * xa.x; accA.y += myA * xa.y;
                    accA.z += myA * xa.z; accA.w += myA * xa.w;
                    accB.x += myA * xb.x; accB.y += myA * xb.y;
                    accB.z += myA * xb.z; accB.w += myA * xb.w;
                }
            }
        }
    } else {
        // ---- fallback: 3-pass gather (deg > 128) ----
        float m0 = -1e30f, m1 = -1e30f, m2 = -1e30f, m3 = -1e30f;
        for (int idx = beg + lane; idx < end; idx += 32) {
            int s = g_src[idx];
            float4 as4 = *(const float4*)&als[s * 4];
            m0 = fmaxf(m0, lrelu(as4.x + ad.x));
            m1 = fmaxf(m1, lrelu(as4.y + ad.y));
            m2 = fmaxf(m2, lrelu(as4.z + ad.z));
            m3 = fmaxf(m3, lrelu(as4.w + ad.w));
        }
#pragma unroll
        for (int off = 16; off; off >>= 1) {
            m0 = fmaxf(m0, __shfl_xor_sync(FULL, m0, off));
            m1 = fmaxf(m1, __shfl_xor_sync(FULL, m1, off));
            m2 = fmaxf(m2, __shfl_xor_sync(FULL, m2, off));
            m3 = fmaxf(m3, __shfl_xor_sync(FULL, m3, off));
        }
        float s0 = 0.f, s1 = 0.f, s2 = 0.f, s3 = 0.f;
        for (int idx = beg + lane; idx < end; idx += 32) {
            int s = g_src[idx];
            float4 as4 = *(const float4*)&als[s * 4];
            s0 += expf(lrelu(as4.x + ad.x) - m0);
            s1 += expf(lrelu(as4.y + ad.y) - m1);
            s2 += expf(lrelu(as4.z + ad.z) - m2);
            s3 += expf(lrelu(as4.w + ad.w) - m3);
        }
#pragma unroll
        for (int off = 16; off; off >>= 1) {
            s0 += __shfl_xor_sync(FULL, s0, off);
            s1 += __shfl_xor_sync(FULL, s1, off);
            s2 += __shfl_xor_sync(FULL, s2, off);
            s3 += __shfl_xor_sync(FULL, s3, off);
        }
        i0 = 1.f / (s0 + 1e-16f); i1 = 1.f / (s1 + 1e-16f);
        i2 = 1.f / (s2 + 1e-16f); i3 = 1.f / (s3 + 1e-16f);
        for (int idx = beg; idx < end; idx++) {
            int e = g_eid[idx];
            int s = g_src[idx];
            float4 as4 = *(const float4*)&als[s * 4];
            float a0 = expf(lrelu(as4.x + ad.x) - m0) * i0;
            float a1 = expf(lrelu(as4.y + ad.y) - m1) * i1;
            float a2 = expf(lrelu(as4.z + ad.z) - m2) * i2;
            float a3 = expf(lrelu(as4.w + ad.w) - m3) * i3;
            if (lane < 4) {
                float av = (lane == 0) ? a0 : (lane == 1) ? a1 : (lane == 2) ? a2 : a3;
                alpha_out[(size_t)e * 4 + lane] = av;
            }
            float myA = (head == 0) ? a0 : (head == 1) ? a1 : (head == 2) ? a2 : a3;
            const float4* xr = (const float4*)&xw[(size_t)s * 256 + lane * 8];
            float4 xa = xr[0], xb = xr[1];
            accA.x += myA * xa.x; accA.y += myA * xa.y;
            accA.z += myA * xa.z; accA.w += myA * xa.w;
            accB.x += myA * xb.x; accB.y += myA * xb.y;
            accB.z += myA * xb.z; accB.w += myA * xb.w;
        }
    }

    // ---- epilogue ----
    if (mode == 0) {
        int c = lane * 8;
        float4 bA = *(const float4*)&bias[c];
        float4 bB = *(const float4*)&bias[c + 4];
        float4 oA = make_float4(fmaxf(accA.x + bA.x, 0.f), fmaxf(accA.y + bA.y, 0.f),
                                fmaxf(accA.z + bA.z, 0.f), fmaxf(accA.w + bA.w, 0.f));
        float4 oB = make_float4(fmaxf(accB.x + bB.x, 0.f), fmaxf(accB.y + bB.y, 0.f),
                                fmaxf(accB.z + bB.z, 0.f), fmaxf(accB.w + bB.w, 0.f));
        *(float4*)&hout[(size_t)n * 256 + c] = oA;
        *(float4*)&hout[(size_t)n * 256 + c + 4] = oB;
    } else {
        // sum across heads: lanes differing in bits 3,4 hold the other heads' copies
#pragma unroll
        for (int off = 8; off <= 16; off <<= 1) {
            accA.x += __shfl_xor_sync(FULL, accA.x, off);
            accA.y += __shfl_xor_sync(FULL, accA.y, off);
            accA.z += __shfl_xor_sync(FULL, accA.z, off);
            accA.w += __shfl_xor_sync(FULL, accA.w, off);
            accB.x += __shfl_xor_sync(FULL, accB.x, off);
            accB.y += __shfl_xor_sync(FULL, accB.y, off);
            accB.z += __shfl_xor_sync(FULL, accB.z, off);
            accB.w += __shfl_xor_sync(FULL, accB.w, off);
        }
        if (lane < 8) {
            int c = lane * 8;
            float4 bA = *(const float4*)&bias[c];
            float4 bB = *(const float4*)&bias[c + 4];
            float4 oA = make_float4(accA.x * 0.25f + bA.x, accA.y * 0.25f + bA.y,
                                    accA.z * 0.25f + bA.z, accA.w * 0.25f + bA.w);
            float4 oB = make_float4(accB.x * 0.25f + bB.x, accB.y * 0.25f + bB.y,
                                    accB.z * 0.25f + bB.z, accB.w * 0.25f + bB.w);
            if (mode == 1) {
                oA = make_float4(fmaxf(oA.x, 0.f), fmaxf(oA.y, 0.f), fmaxf(oA.z, 0.f), fmaxf(oA.w, 0.f));
                oB = make_float4(fmaxf(oB.x, 0.f), fmaxf(oB.y, 0.f), fmaxf(oB.z, 0.f), fmaxf(oB.w, 0.f));
            }
            *(float4*)&hout[(size_t)n * 64 + c] = oA;
            *(float4*)&hout[(size_t)n * 64 + c + 4] = oB;
        }
    }
}

// ---------------- host ----------------
extern "C" void kernel_launch(void* const* d_in, const int* in_sizes, int n_in,
                              void* d_out, int out_size) {
    const float* x      = (const float*)d_in[0];
    const int*   ei     = (const int*)d_in[1];
    const float* gcn_W  = (const float*)d_in[2];
    const float* gcn_b  = (const float*)d_in[3];
    const float* g1_W   = (const float*)d_in[4];
    const float* g1_as  = (const float*)d_in[5];
    const float* g1_ad  = (const float*)d_in[6];
    const float* g1_b   = (const float*)d_in[7];
    const float* g2_W   = (const float*)d_in[8];
    const float* g2_as  = (const float*)d_in[9];
    const float* g2_ad  = (const float*)d_in[10];
    const float* g2_b   = (const float*)d_in[11];
    const float* m_W    = (const float*)d_in[12];
    const float* m_as   = (const float*)d_in[13];
    const float* m_ad   = (const float*)d_in[14];
    const float* m_b    = (const float*)d_in[15];
    const float* s_W    = (const float*)d_in[16];
    const float* s_as   = (const float*)d_in[17];
    const float* s_ad   = (const float*)d_in[18];
    const float* s_b    = (const float*)d_in[19];

    float* out    = (float*)d_out;
    float* z_mean = out;
    float* z_std  = out + (size_t)NNODES * 64;
    float* a1     = out + (size_t)NNODES * 128;
    float* a2     = a1 + (size_t)EPRIME * 4;
    float* am     = a2 + (size_t)EPRIME * 4;
    float* as     = am + (size_t)EPRIME * 4;

    float *p_xw, *p_xw2, *p_h0, *p_h1, *p_h2;
    float *p_als, *p_ald, *p_als2, *p_ald2;
    int   *p_deg;
    cudaGetSymbolAddress((void**)&p_xw,  g_xw);
    cudaGetSymbolAddress((void**)&p_xw2, g_xw2);
    cudaGetSymbolAddress((void**)&p_h0,  g_h0);
    cudaGetSymbolAddress((void**)&p_h1,  g_h1);
    cudaGetSymbolAddress((void**)&p_h2,  g_h2);
    cudaGetSymbolAddress((void**)&p_als, g_als);
    cudaGetSymbolAddress((void**)&p_ald, g_ald);
    cudaGetSymbolAddress((void**)&p_als2, g_als2);
    cudaGetSymbolAddress((void**)&p_ald2, g_ald2);
    cudaGetSymbolAddress((void**)&p_deg, g_deg);

    const int TB = 256;
    int edgeBlocks = (EPRIME + TB - 1) / TB;             // elementwise over edges
    int warpBlocks = (NNODES * 32 + TB - 1) / TB;        // one warp per node

    dim3 g64(1, (NNODES + 127) / 128), g256(4, (NNODES + 127) / 128);

    // ---- fork: GCN GEMM on s2 (independent of CSR build) ----
    cudaEventRecord(g_ev0, 0);
    cudaStreamWaitEvent(g_s2, g_ev0, 0);
    k_sgemm<<<g64, 256, 0, g_s2>>>(x, gcn_W, p_xw, NNODES, 64, 128,
                                   nullptr, nullptr, nullptr, nullptr);
    cudaEventRecord(g_ev1, g_s2);

    // ---- CSR build on default stream (runs concurrently) ----
    cudaMemsetAsync(p_deg, 0, NNODES * sizeof(int));
    k_count<<<edgeBlocks, TB>>>(ei);
    k_scan<<<1, 1024>>>();
    k_scatter<<<edgeBlocks, TB>>>(ei);

    // join: k_gcn needs both CSR and xw
    cudaStreamWaitEvent(0, g_ev1, 0);
    k_gcn<<<warpBlocks, TB>>>(p_xw, gcn_b);

    // GAT1 (concat + relu) — attn fused into GEMM epilogue
    k_sgemm<<<g256, 256>>>(p_h0, g1_W, p_xw, NNODES, 256, 64,
                           g1_as, g1_ad, p_als, p_ald);
    k_gat<<<warpBlocks, TB>>>(p_xw, g1_b, a1, p_h1, 0, p_als, p_ald);

    // GAT2 (mean + relu)
    k_sgemm<<<g256, 256>>>(p_h1, g2_W, p_xw, NNODES, 256, 256,
                           g2_as, g2_ad, p_als, p_ald);
    k_gat<<<warpBlocks, TB>>>(p_xw, g2_b, a2, p_h2, 1, p_als, p_ald);

    // ---- fork: std chain on s2, mean chain on default stream ----
    cudaEventRecord(g_ev2, 0);
    cudaStreamWaitEvent(g_s2, g_ev2, 0);

    // std head (mean, no relu) on s2, private scratch
    k_sgemm<<<g256, 256, 0, g_s2>>>(p_h2, s_W, p_xw2, NNODES, 256, 64,
                                    s_as, s_ad, p_als2, p_ald2);
    k_gat<<<warpBlocks, TB, 0, g_s2>>>(p_xw2, s_b, as, z_std, 2, p_als2, p_ald2);
    cudaEventRecord(g_ev3, g_s2);

    // mean head (mean, no relu) on default stream
    k_sgemm<<<g256, 256>>>(p_h2, m_W, p_xw, NNODES, 256, 64,
                           m_as, m_ad, p_als, p_ald);
    k_gat<<<warpBlocks, TB>>>(p_xw, m_b, am, z_mean, 2, p_als, p_ald);

    // join
    cudaStreamWaitEvent(0, g_ev3, 0);
}